// round 2
// baseline (speedup 1.0000x reference)
#include <cuda_runtime.h>
#include <math.h>

#define BATCH 8
#define T 512
#define D 512
#define H 8
#define HS 64
#define BT (BATCH*T)     // 4096
#define FF 2048

// ---------------- device scratch (no allocations allowed) ----------------
__device__ float g_x[BT*D];       // rmsnorm(src)
__device__ float g_w3[3*D*D];     // packed Wq,Wk,Wv as [D, H*HS]
__device__ float g_q[BT*D];       // [b*T+t][h*64+c]
__device__ float g_k[BT*D];
__device__ float g_v[BT*D];
__device__ float g_att[BT*D];     // attention output, concat heads
__device__ float g_src2[BT*D];    // x + proj(att)
__device__ float g_y[BT*D];       // rmsnorm(src2)
__device__ float g_h[BT*FF];      // ff hidden

// ---------------- rmsnorm: one block per row, 128 threads x float4 -------
__global__ __launch_bounds__(128) void rmsnorm_kernel(
    const float* __restrict__ in, const float* __restrict__ w, float* __restrict__ out)
{
    int row = blockIdx.x;
    int tid = threadIdx.x;
    const float4 v = ((const float4*)(in + (size_t)row * D))[tid];
    float ss = v.x*v.x + v.y*v.y + v.z*v.z + v.w*v.w;
    #pragma unroll
    for (int o = 16; o > 0; o >>= 1) ss += __shfl_xor_sync(0xffffffffu, ss, o);
    __shared__ float ws[4];
    if ((tid & 31) == 0) ws[tid >> 5] = ss;
    __syncthreads();
    float total = ws[0] + ws[1] + ws[2] + ws[3];
    float r = rsqrtf(total * (1.0f / (float)D) + 1e-6f);
    const float4 wv = ((const float4*)w)[tid];
    float4 o;
    o.x = v.x * r * wv.x;
    o.y = v.y * r * wv.y;
    o.z = v.z * r * wv.z;
    o.w = v.w * r * wv.w;
    ((float4*)(out + (size_t)row * D))[tid] = o;
}

// ---------------- pack Wq/Wk/Wv [H,D,HS] -> [D, H*HS] ---------------------
__global__ void pack_qkv_kernel(const float* __restrict__ Wq,
                                const float* __restrict__ Wk,
                                const float* __restrict__ Wv)
{
    int idx = blockIdx.x * 256 + threadIdx.x;
    if (idx >= 3 * D * D) return;
    int mat = idx / (D * D);
    int r   = idx % (D * D);
    int d   = r / D;
    int n   = r % D;
    const float* W = (mat == 0) ? Wq : (mat == 1) ? Wk : Wv;
    // W[h][d][c] with h = n>>6, c = n&63
    g_w3[idx] = W[((n >> 6) * D + d) * HS + (n & 63)];
}

// ---------------- generic fp32 GEMM, BM=128 BN=64 BK=16, 256 threads -----
// C[M,N] = A[M,K] @ B[K,N] + bias[N]  (+residual) (+exact GELU)
template<bool RESID, bool GELU>
__global__ __launch_bounds__(256) void gemm_kernel(
    const float* __restrict__ A, const float* __restrict__ B,
    const float* __restrict__ bias, const float* __restrict__ R,
    float* __restrict__ C, int M, int N, int K)
{
    __shared__ float As[16][132];   // padded, 16B-aligned rows (528B)
    __shared__ float Bs[16][68];    // padded, 16B-aligned rows (272B)

    const int bm = blockIdx.y * 128;
    const int bn = blockIdx.x * 64;
    const int tid = threadIdx.x;
    const int row0 = (tid >> 4) * 8;   // 0..120
    const int col0 = (tid & 15) * 4;   // 0..60
    const int ar = tid >> 2;           // 0..63 (A tile row, +64 for 2nd)
    const int ak = (tid & 3) * 4;      // A tile k offset
    const int br = tid >> 4;           // 0..15 (B tile row)
    const int bc = (tid & 15) * 4;     // B tile col

    float acc[8][4];
    #pragma unroll
    for (int i = 0; i < 8; i++)
        #pragma unroll
        for (int j = 0; j < 4; j++) acc[i][j] = 0.f;

    for (int k0 = 0; k0 < K; k0 += 16) {
        float4 a0 = *(const float4*)(A + (size_t)(bm + ar)      * K + k0 + ak);
        float4 a1 = *(const float4*)(A + (size_t)(bm + ar + 64) * K + k0 + ak);
        float4 b0 = *(const float4*)(B + (size_t)(k0 + br) * N + bn + bc);
        As[ak+0][ar]    = a0.x; As[ak+1][ar]    = a0.y; As[ak+2][ar]    = a0.z; As[ak+3][ar]    = a0.w;
        As[ak+0][ar+64] = a1.x; As[ak+1][ar+64] = a1.y; As[ak+2][ar+64] = a1.z; As[ak+3][ar+64] = a1.w;
        *(float4*)&Bs[br][bc] = b0;
        __syncthreads();
        #pragma unroll
        for (int kk = 0; kk < 16; kk++) {
            float4 av0 = *(const float4*)&As[kk][row0];
            float4 av1 = *(const float4*)&As[kk][row0 + 4];
            float4 bv  = *(const float4*)&Bs[kk][col0];
            float a[8] = {av0.x, av0.y, av0.z, av0.w, av1.x, av1.y, av1.z, av1.w};
            float b[4] = {bv.x, bv.y, bv.z, bv.w};
            #pragma unroll
            for (int i = 0; i < 8; i++)
                #pragma unroll
                for (int j = 0; j < 4; j++)
                    acc[i][j] = fmaf(a[i], b[j], acc[i][j]);
        }
        __syncthreads();
    }

    float bb[4];
    #pragma unroll
    for (int j = 0; j < 4; j++) bb[j] = bias[bn + col0 + j];

    #pragma unroll
    for (int i = 0; i < 8; i++) {
        int m = bm + row0 + i;
        float vals[4];
        #pragma unroll
        for (int j = 0; j < 4; j++) {
            float cv = acc[i][j] + bb[j];
            if (RESID) cv += R[(size_t)m * N + bn + col0 + j];
            if (GELU)  cv = 0.5f * cv * (1.f + erff(cv * 0.70710678118654752f));
            vals[j] = cv;
        }
        float4 o; o.x = vals[0]; o.y = vals[1]; o.z = vals[2]; o.w = vals[3];
        *(float4*)(C + (size_t)m * N + bn + col0) = o;
    }
}

// ---------------- fused attention: one block per (t, h) ------------------
// scores[b][v] = sqrt(HS)*(q.k) + q.rel = q . (8*k + rel); softmax; out = att@V
__global__ __launch_bounds__(256) void attn_kernel(const float* __restrict__ relp)
{
    const int t = blockIdx.x;
    const int h = blockIdx.y;
    const int tid = threadIdx.x;

    __shared__ float4 qs4[8 * 16];    // q[b][c4], 2KB
    __shared__ float ss[8][512];      // scores/probs, 16KB

    if (tid < 128) {
        int b = tid >> 4, c4 = tid & 15;
        qs4[tid] = *(const float4*)(g_q + ((size_t)(b * T + t)) * D + h * HS + c4 * 4);
    }
    __syncthreads();

    // ---- scores: each thread handles 2 v-values, all 8 batches (rel read once) ----
    #pragma unroll
    for (int i = 0; i < 2; i++) {
        const int v = tid + i * 256;
        const float4* rel4 = (const float4*)(relp + (((size_t)h * T + t) * T + v) * HS);
        const float* kbase = g_k + (size_t)v * D + h * HS;
        float acc[8];
        #pragma unroll
        for (int b = 0; b < 8; b++) acc[b] = 0.f;
        #pragma unroll 2
        for (int c4 = 0; c4 < 16; c4++) {
            float4 r = rel4[c4];
            #pragma unroll
            for (int b = 0; b < 8; b++) {
                float4 q  = qs4[b * 16 + c4];
                float4 kk = *(const float4*)(kbase + (size_t)b * (T * D) + c4 * 4);
                acc[b] = fmaf(q.x, fmaf(8.f, kk.x, r.x), acc[b]);
                acc[b] = fmaf(q.y, fmaf(8.f, kk.y, r.y), acc[b]);
                acc[b] = fmaf(q.z, fmaf(8.f, kk.z, r.z), acc[b]);
                acc[b] = fmaf(q.w, fmaf(8.f, kk.w, r.w), acc[b]);
            }
        }
        #pragma unroll
        for (int b = 0; b < 8; b++) ss[b][v] = acc[b];
    }
    __syncthreads();

    // ---- softmax: warp w owns batch row b=w ----
    {
        const int w = tid >> 5, lane = tid & 31;
        float m = -1e30f;
        #pragma unroll
        for (int j = lane; j < 512; j += 32) m = fmaxf(m, ss[w][j]);
        #pragma unroll
        for (int o = 16; o > 0; o >>= 1) m = fmaxf(m, __shfl_xor_sync(0xffffffffu, m, o));
        float s = 0.f;
        #pragma unroll
        for (int j = lane; j < 512; j += 32) {
            float e = __expf(ss[w][j] - m);
            ss[w][j] = e;
            s += e;
        }
        #pragma unroll
        for (int o = 16; o > 0; o >>= 1) s += __shfl_xor_sync(0xffffffffu, s, o);
        const float inv = 1.f / s;
        #pragma unroll
        for (int j = lane; j < 512; j += 32) ss[w][j] *= inv;
    }
    __syncthreads();

    // ---- out = att @ V : warp b, each thread covers 2 head-channels ----
    {
        const int b = tid >> 5;
        const int c = (tid & 31) * 2;
        const float* vbase = g_v + (size_t)b * (T * D) + h * HS + c;
        float a0 = 0.f, a1 = 0.f;
        #pragma unroll 8
        for (int v = 0; v < 512; v++) {
            float2 vv = *(const float2*)(vbase + (size_t)v * D);
            float a = ss[b][v];
            a0 = fmaf(a, vv.x, a0);
            a1 = fmaf(a, vv.y, a1);
        }
        float2 o; o.x = a0; o.y = a1;
        *(float2*)(g_att + ((size_t)(b * T + t)) * D + h * HS + c) = o;
    }
}

// ---------------- launch ---------------------------------------------------
extern "C" void kernel_launch(void* const* d_in, const int* in_sizes, int n_in,
                              void* d_out, int out_size)
{
    (void)in_sizes; (void)n_in; (void)out_size;
    const float* src    = (const float*)d_in[0];
    const float* norm_w = (const float*)d_in[1];
    const float* Wq     = (const float*)d_in[2];
    const float* bq     = (const float*)d_in[3];
    const float* Wk     = (const float*)d_in[4];
    const float* bk     = (const float*)d_in[5];
    const float* Wv     = (const float*)d_in[6];
    const float* bv     = (const float*)d_in[7];
    const float* relp   = (const float*)d_in[8];
    const float* proj_w = (const float*)d_in[9];
    const float* proj_b = (const float*)d_in[10];
    const float* ff_w1  = (const float*)d_in[11];
    const float* ff_b1  = (const float*)d_in[12];
    const float* ff_w2  = (const float*)d_in[13];
    const float* ff_b2  = (const float*)d_in[14];
    float* out = (float*)d_out;

    float *px, *pw3, *pq, *pk, *pv, *patt, *psrc2, *py, *ph;
    cudaGetSymbolAddress((void**)&px,    g_x);
    cudaGetSymbolAddress((void**)&pw3,   g_w3);
    cudaGetSymbolAddress((void**)&pq,    g_q);
    cudaGetSymbolAddress((void**)&pk,    g_k);
    cudaGetSymbolAddress((void**)&pv,    g_v);
    cudaGetSymbolAddress((void**)&patt,  g_att);
    cudaGetSymbolAddress((void**)&psrc2, g_src2);
    cudaGetSymbolAddress((void**)&py,    g_y);
    cudaGetSymbolAddress((void**)&ph,    g_h);

    // 1. pack QKV weights
    pack_qkv_kernel<<<(3 * D * D + 255) / 256, 256>>>(Wq, Wk, Wv);
    // 2. x = rmsnorm(src)
    rmsnorm_kernel<<<BT, 128>>>(src, norm_w, px);
    // 3-5. q,k,v = x @ W{q,k,v} + b  (N=512 layout: [bt][h*64+c])
    dim3 g1(D / 64, BT / 128);              // (8, 32)
    gemm_kernel<false, false><<<g1, 256>>>(px, pw3,             bq, nullptr, pq, BT, D, D);
    gemm_kernel<false, false><<<g1, 256>>>(px, pw3 + D * D,     bk, nullptr, pk, BT, D, D);
    gemm_kernel<false, false><<<g1, 256>>>(px, pw3 + 2 * D * D, bv, nullptr, pv, BT, D, D);
    // 6. fused attention (scores + rel + softmax + A@V)
    attn_kernel<<<dim3(T, H), 256>>>(relp);
    // 7. src2 = x + att @ proj_w + proj_b
    gemm_kernel<true, false><<<g1, 256>>>(patt, proj_w, proj_b, px, psrc2, BT, D, D);
    // 8. y = rmsnorm(src2)
    rmsnorm_kernel<<<BT, 128>>>(psrc2, norm_w, py);
    // 9. h = gelu(y @ ff_w1 + ff_b1)
    dim3 g2(FF / 64, BT / 128);             // (32, 32)
    gemm_kernel<false, true><<<g2, 256>>>(py, ff_w1, ff_b1, nullptr, ph, BT, FF, D);
    // 10. out = y + h @ ff_w2 + ff_b2
    gemm_kernel<true, false><<<g1, 256>>>(ph, ff_w2, ff_b2, py, out, BT, D, FF);
}

// round 4
// speedup vs baseline: 1.2747x; 1.2747x over previous
#include <cuda_runtime.h>
#include <cuda_bf16.h>
#include <math.h>
#include <stdint.h>

#define BATCH 8
#define T 512
#define D 512
#define H 8
#define HS 64
#define BT (BATCH*T)     // 4096
#define FF 2048

// ===================== device scratch =====================
__device__ __align__(16) float g_x[BT*D];
__device__ __align__(16) float g_q[BT*D];
__device__ __align__(16) float g_k[BT*D];
__device__ __align__(16) float g_v[BT*D];
__device__ __align__(16) float g_src2[BT*D];
__device__ __align__(16) float g_y[BT*D];
__device__ __align__(16) __nv_bfloat16 g_xh[BT*D],  g_xl[BT*D];
__device__ __align__(16) __nv_bfloat16 g_yh[BT*D],  g_yl[BT*D];
__device__ __align__(16) __nv_bfloat16 g_atth[BT*D], g_attl[BT*D];
__device__ __align__(16) __nv_bfloat16 g_hh[BT*FF], g_hl[BT*FF];
__device__ __align__(16) __nv_bfloat16 g_w3h[3*D*D], g_w3l[3*D*D];   // [mat][n][k]
__device__ __align__(16) __nv_bfloat16 g_pwh[D*D],  g_pwl[D*D];      // [n][k]
__device__ __align__(16) __nv_bfloat16 g_f1h[FF*D], g_f1l[FF*D];     // [n=2048][k=512]
__device__ __align__(16) __nv_bfloat16 g_f2h[D*FF], g_f2l[D*FF];     // [n=512][k=2048]

__device__ __forceinline__ void split2(float v, __nv_bfloat16& h, __nv_bfloat16& l) {
    h = __float2bfloat16(v);
    l = __float2bfloat16(v - __bfloat162float(h));
}

// ===================== warp-MMA primitives (baseline PTX, sm_80+) ==========
__device__ __forceinline__ void mma_bf16(float* d, const uint32_t* a, const uint32_t* b) {
    asm volatile(
        "mma.sync.aligned.m16n8k16.row.col.f32.bf16.bf16.f32 "
        "{%0,%1,%2,%3}, {%4,%5,%6,%7}, {%8,%9}, {%0,%1,%2,%3};"
        : "+f"(d[0]), "+f"(d[1]), "+f"(d[2]), "+f"(d[3])
        : "r"(a[0]), "r"(a[1]), "r"(a[2]), "r"(a[3]), "r"(b[0]), "r"(b[1]));
}
__device__ __forceinline__ void ldsm4(uint32_t* r, uint32_t addr) {
    asm volatile("ldmatrix.sync.aligned.m8n8.x4.shared.b16 {%0,%1,%2,%3}, [%4];"
        : "=r"(r[0]), "=r"(r[1]), "=r"(r[2]), "=r"(r[3]) : "r"(addr));
}
__device__ __forceinline__ uint32_t smem_to_u32(const void* p) {
    uint32_t a;
    asm("{ .reg .u64 t; cvta.to.shared.u64 t, %1; cvt.u32.u64 %0, t; }" : "=r"(a) : "l"(p));
    return a;
}

// ===================== weight prep =====================
// generic: W[K,N] row-major -> Wt_hi/lo [N,K]
__global__ void wsplit_kernel(const float* __restrict__ W,
                              __nv_bfloat16* __restrict__ Wh, __nv_bfloat16* __restrict__ Wl,
                              int K, int N)
{
    int idx = blockIdx.x * 256 + threadIdx.x;
    if (idx >= K * N) return;
    int n = idx / K, k = idx % K;
    float v = W[(size_t)k * N + n];
    __nv_bfloat16 h, l; split2(v, h, l);
    Wh[idx] = h; Wl[idx] = l;
}

// qkv: W[h][d][c] -> [mat][n=h*64+c][k=d]
__global__ void wsplit_qkv_kernel(const float* __restrict__ Wq,
                                  const float* __restrict__ Wk,
                                  const float* __restrict__ Wv)
{
    int idx = blockIdx.x * 256 + threadIdx.x;
    if (idx >= 3 * D * D) return;
    int mat = idx / (D * D);
    int r   = idx % (D * D);
    int n = r / D, k = r % D;
    const float* W = (mat == 0) ? Wq : (mat == 1) ? Wk : Wv;
    float v = W[(((size_t)(n >> 6)) * D + k) * HS + (n & 63)];
    __nv_bfloat16 h, l; split2(v, h, l);
    g_w3h[idx] = h; g_w3l[idx] = l;
}

// ===================== rmsnorm (emits float + hi/lo bf16) =====================
__global__ __launch_bounds__(128) void rmsnorm_kernel(
    const float* __restrict__ in, const float* __restrict__ w,
    float* __restrict__ out, __nv_bfloat16* __restrict__ outh, __nv_bfloat16* __restrict__ outl)
{
    int row = blockIdx.x;
    int tid = threadIdx.x;
    const float4 v = ((const float4*)(in + (size_t)row * D))[tid];
    float ss = v.x*v.x + v.y*v.y + v.z*v.z + v.w*v.w;
    #pragma unroll
    for (int o = 16; o > 0; o >>= 1) ss += __shfl_xor_sync(0xffffffffu, ss, o);
    __shared__ float ws[4];
    if ((tid & 31) == 0) ws[tid >> 5] = ss;
    __syncthreads();
    float total = ws[0] + ws[1] + ws[2] + ws[3];
    float r = rsqrtf(total * (1.0f / (float)D) + 1e-6f);
    const float4 wv = ((const float4*)w)[tid];
    float4 o;
    o.x = v.x * r * wv.x; o.y = v.y * r * wv.y;
    o.z = v.z * r * wv.z; o.w = v.w * r * wv.w;
    ((float4*)(out + (size_t)row * D))[tid] = o;
    __nv_bfloat16 h0,l0,h1,l1,h2,l2,h3,l3;
    split2(o.x,h0,l0); split2(o.y,h1,l1); split2(o.z,h2,l2); split2(o.w,h3,l3);
    __nv_bfloat162 hA; hA.x=h0; hA.y=h1;
    __nv_bfloat162 hB; hB.x=h2; hB.y=h3;
    __nv_bfloat162 lA; lA.x=l0; lA.y=l1;
    __nv_bfloat162 lB; lB.x=l2; lB.y=l3;
    size_t base = (size_t)row * D + tid * 4;
    *(__nv_bfloat162*)(outh + base)     = hA;
    *(__nv_bfloat162*)(outh + base + 2) = hB;
    *(__nv_bfloat162*)(outl + base)     = lA;
    *(__nv_bfloat162*)(outl + base + 2) = lB;
}

// ===================== warp-MMA split-bf16 GEMM ============================
// C[M,N] = AhBh + AhBl + AlBh  (fp32 accum), A:[M,K] hi/lo, B:[N,K] hi/lo
// CTA tile 128x128x32, 8 warps (2M x 4N), warp tile 64x32.
// smem rows padded to 80B -> conflict-free ldmatrix.
static constexpr int TROW   = 80;            // bytes per smem row (32 bf16 used)
static constexpr int TILEB  = 128 * TROW;    // 10240 per tensor tile
static constexpr int STAGEB = 4 * TILEB;     // 40960 per stage (Ah,Al,Bh,Bl)
static constexpr int GEMM_SMEM = 2 * STAGEB; // 81920

template<bool RESID, bool GELU, bool OUTF, bool OUTS>
__global__ __launch_bounds__(256, 1) void gemm_mma(
    const __nv_bfloat16* __restrict__ Ah, const __nv_bfloat16* __restrict__ Al,
    const __nv_bfloat16* __restrict__ Bh, const __nv_bfloat16* __restrict__ Bl,
    const float* __restrict__ bias, const float* __restrict__ R,
    float* __restrict__ C, __nv_bfloat16* __restrict__ Ch, __nv_bfloat16* __restrict__ Cl,
    int M, int N, int K)
{
    extern __shared__ char sm[];
    const int tid  = threadIdx.x;
    const int wid  = tid >> 5, lane = tid & 31;
    const int warpM = wid & 1, warpN = wid >> 1;
    const int bm = blockIdx.y * 128, bn = blockIdx.x * 128;
    const uint32_t smb = smem_to_u32(sm);

    const int lrow   = tid >> 2;      // 0..63
    const int lchunk = tid & 3;       // 0..3 (16B chunks)
    const int soff   = lrow * TROW + lchunk * 16;

    // ldmatrix per-lane byte offsets within a tensor tile
    const int a_off = (warpM * 64 + (lane & 15)) * TROW + (lane >> 4) * 16;
    const int b_off = (warpN * 32 + ((lane >> 4) << 3) + (lane & 7)) * TROW + ((lane >> 3) & 1) * 16;

    float acc[4][4][4];
    #pragma unroll
    for (int i = 0; i < 4; i++)
        #pragma unroll
        for (int j = 0; j < 4; j++)
            #pragma unroll
            for (int r = 0; r < 4; r++) acc[i][j][r] = 0.f;

    const int nch = K >> 5;
    uint4 pf[8];

    auto ldg = [&](int c) {
        const int k0 = c << 5;
        const __nv_bfloat16* pa  = Ah + (size_t)(bm + lrow) * K + k0 + lchunk * 8;
        const __nv_bfloat16* pal = Al + (size_t)(bm + lrow) * K + k0 + lchunk * 8;
        const __nv_bfloat16* pb  = Bh + (size_t)(bn + lrow) * K + k0 + lchunk * 8;
        const __nv_bfloat16* pbl = Bl + (size_t)(bn + lrow) * K + k0 + lchunk * 8;
        pf[0] = *(const uint4*)pa;
        pf[1] = *(const uint4*)(pa + (size_t)64 * K);
        pf[2] = *(const uint4*)pal;
        pf[3] = *(const uint4*)(pal + (size_t)64 * K);
        pf[4] = *(const uint4*)pb;
        pf[5] = *(const uint4*)(pb + (size_t)64 * K);
        pf[6] = *(const uint4*)pbl;
        pf[7] = *(const uint4*)(pbl + (size_t)64 * K);
    };

    ldg(0);
    int p = 0;
    for (int c = 0; c < nch; ++c) {
        char* st = sm + p * STAGEB;
        *(uint4*)(st + soff)                       = pf[0];
        *(uint4*)(st + soff + 64 * TROW)           = pf[1];
        *(uint4*)(st + TILEB   + soff)             = pf[2];
        *(uint4*)(st + TILEB   + soff + 64 * TROW) = pf[3];
        *(uint4*)(st + 2*TILEB + soff)             = pf[4];
        *(uint4*)(st + 2*TILEB + soff + 64 * TROW) = pf[5];
        *(uint4*)(st + 3*TILEB + soff)             = pf[6];
        *(uint4*)(st + 3*TILEB + soff + 64 * TROW) = pf[7];
        __syncthreads();
        if (c + 1 < nch) ldg(c + 1);

        const uint32_t sb = smb + p * STAGEB;
        #pragma unroll
        for (int ks = 0; ks < 2; ++ks) {
            uint32_t ahr[4][4], alr[4][4], bhr[2][4], blr[2][4];
            #pragma unroll
            for (int i = 0; i < 4; ++i) {
                ldsm4(ahr[i], sb + a_off + i * (16 * TROW) + ks * 32);
                ldsm4(alr[i], sb + TILEB + a_off + i * (16 * TROW) + ks * 32);
            }
            #pragma unroll
            for (int j = 0; j < 2; ++j) {
                ldsm4(bhr[j], sb + 2*TILEB + b_off + j * (16 * TROW) + ks * 32);
                ldsm4(blr[j], sb + 3*TILEB + b_off + j * (16 * TROW) + ks * 32);
            }
            #pragma unroll
            for (int i = 0; i < 4; ++i)
                #pragma unroll
                for (int j = 0; j < 4; ++j) {
                    uint32_t bfh[2] = { bhr[j >> 1][(j & 1) * 2], bhr[j >> 1][(j & 1) * 2 + 1] };
                    uint32_t bfl[2] = { blr[j >> 1][(j & 1) * 2], blr[j >> 1][(j & 1) * 2 + 1] };
                    mma_bf16(acc[i][j], ahr[i], bfh);
                    mma_bf16(acc[i][j], ahr[i], bfl);
                    mma_bf16(acc[i][j], alr[i], bfh);
                }
        }
        p ^= 1;
    }

    // ---- epilogue ----
    #pragma unroll
    for (int i = 0; i < 4; ++i) {
        const int m0 = bm + warpM * 64 + i * 16 + (lane >> 2);
        #pragma unroll
        for (int j = 0; j < 4; ++j) {
            const int n = bn + warpN * 32 + j * 8 + (lane & 3) * 2;
            const float b0 = bias[n], b1 = bias[n + 1];
            #pragma unroll
            for (int rr = 0; rr < 2; ++rr) {
                const int m = m0 + rr * 8;
                float v0 = acc[i][j][rr * 2 + 0] + b0;
                float v1 = acc[i][j][rr * 2 + 1] + b1;
                if (RESID) {
                    const float2 rv = *(const float2*)(R + (size_t)m * N + n);
                    v0 += rv.x; v1 += rv.y;
                }
                if (GELU) {
                    v0 = 0.5f * v0 * (1.f + erff(v0 * 0.70710678118654752f));
                    v1 = 0.5f * v1 * (1.f + erff(v1 * 0.70710678118654752f));
                }
                if (OUTF) {
                    float2 o; o.x = v0; o.y = v1;
                    *(float2*)(C + (size_t)m * N + n) = o;
                }
                if (OUTS) {
                    __nv_bfloat16 h0, l0, h1, l1;
                    split2(v0, h0, l0); split2(v1, h1, l1);
                    __nv_bfloat162 hv; hv.x = h0; hv.y = h1;
                    __nv_bfloat162 lv; lv.x = l0; lv.y = l1;
                    *(__nv_bfloat162*)(Ch + (size_t)m * N + n) = hv;
                    *(__nv_bfloat162*)(Cl + (size_t)m * N + n) = lv;
                }
            }
        }
    }
}

// ===================== fused attention (fp32) ==============================
// scores[b][v] = sqrt(HS)*(q.k) + q.rel = q . (8*k + rel); softmax; out = att@V
__global__ __launch_bounds__(256) void attn_kernel(const float* __restrict__ relp)
{
    const int t = blockIdx.x;
    const int h = blockIdx.y;
    const int tid = threadIdx.x;

    __shared__ float4 qs4[8 * 16];
    __shared__ float ss[8][512];

    if (tid < 128) {
        int b = tid >> 4, c4 = tid & 15;
        qs4[tid] = *(const float4*)(g_q + ((size_t)(b * T + t)) * D + h * HS + c4 * 4);
    }
    __syncthreads();

    #pragma unroll
    for (int i = 0; i < 2; i++) {
        const int v = tid + i * 256;
        const float4* rel4 = (const float4*)(relp + (((size_t)h * T + t) * T + v) * HS);
        const float* kbase = g_k + (size_t)v * D + h * HS;
        float acc[8];
        #pragma unroll
        for (int b = 0; b < 8; b++) acc[b] = 0.f;
        #pragma unroll 2
        for (int c4 = 0; c4 < 16; c4++) {
            float4 r = rel4[c4];
            #pragma unroll
            for (int b = 0; b < 8; b++) {
                float4 q  = qs4[b * 16 + c4];
                float4 kk = *(const float4*)(kbase + (size_t)b * (T * D) + c4 * 4);
                acc[b] = fmaf(q.x, fmaf(8.f, kk.x, r.x), acc[b]);
                acc[b] = fmaf(q.y, fmaf(8.f, kk.y, r.y), acc[b]);
                acc[b] = fmaf(q.z, fmaf(8.f, kk.z, r.z), acc[b]);
                acc[b] = fmaf(q.w, fmaf(8.f, kk.w, r.w), acc[b]);
            }
        }
        #pragma unroll
        for (int b = 0; b < 8; b++) ss[b][v] = acc[b];
    }
    __syncthreads();

    {
        const int w = tid >> 5, lane = tid & 31;
        float m = -1e30f;
        #pragma unroll
        for (int j = lane; j < 512; j += 32) m = fmaxf(m, ss[w][j]);
        #pragma unroll
        for (int o = 16; o > 0; o >>= 1) m = fmaxf(m, __shfl_xor_sync(0xffffffffu, m, o));
        float s = 0.f;
        #pragma unroll
        for (int j = lane; j < 512; j += 32) {
            float e = __expf(ss[w][j] - m);
            ss[w][j] = e;
            s += e;
        }
        #pragma unroll
        for (int o = 16; o > 0; o >>= 1) s += __shfl_xor_sync(0xffffffffu, s, o);
        const float inv = 1.f / s;
        #pragma unroll
        for (int j = lane; j < 512; j += 32) ss[w][j] *= inv;
    }
    __syncthreads();

    {
        const int b = tid >> 5;
        const int c = (tid & 31) * 2;
        const float* vbase = g_v + (size_t)b * (T * D) + h * HS + c;
        float a0 = 0.f, a1 = 0.f;
        #pragma unroll 8
        for (int v = 0; v < 512; v++) {
            float2 vv = *(const float2*)(vbase + (size_t)v * D);
            float a = ss[b][v];
            a0 = fmaf(a, vv.x, a0);
            a1 = fmaf(a, vv.y, a1);
        }
        __nv_bfloat16 h0, l0, h1, l1;
        split2(a0, h0, l0); split2(a1, h1, l1);
        __nv_bfloat162 hv; hv.x = h0; hv.y = h1;
        __nv_bfloat162 lv; lv.x = l0; lv.y = l1;
        size_t off = ((size_t)(b * T + t)) * D + h * HS + c;
        *(__nv_bfloat162*)(g_atth + off) = hv;
        *(__nv_bfloat162*)(g_attl + off) = lv;
    }
}

// ===================== launch ==============================================
extern "C" void kernel_launch(void* const* d_in, const int* in_sizes, int n_in,
                              void* d_out, int out_size)
{
    (void)in_sizes; (void)n_in; (void)out_size;
    const float* src    = (const float*)d_in[0];
    const float* norm_w = (const float*)d_in[1];
    const float* Wq     = (const float*)d_in[2];
    const float* bq     = (const float*)d_in[3];
    const float* Wk     = (const float*)d_in[4];
    const float* bk     = (const float*)d_in[5];
    const float* Wv     = (const float*)d_in[6];
    const float* bv     = (const float*)d_in[7];
    const float* relp   = (const float*)d_in[8];
    const float* proj_w = (const float*)d_in[9];
    const float* proj_b = (const float*)d_in[10];
    const float* ff_w1  = (const float*)d_in[11];
    const float* ff_b1  = (const float*)d_in[12];
    const float* ff_w2  = (const float*)d_in[13];
    const float* ff_b2  = (const float*)d_in[14];
    float* out = (float*)d_out;

    float *px, *pq, *pk, *pv, *psrc2, *py;
    __nv_bfloat16 *pxh, *pxl, *pyh, *pyl, *patth, *pattl, *phh, *phl;
    __nv_bfloat16 *pw3h, *pw3l, *ppwh, *ppwl, *pf1h, *pf1l, *pf2h, *pf2l;
    cudaGetSymbolAddress((void**)&px,    g_x);
    cudaGetSymbolAddress((void**)&pq,    g_q);
    cudaGetSymbolAddress((void**)&pk,    g_k);
    cudaGetSymbolAddress((void**)&pv,    g_v);
    cudaGetSymbolAddress((void**)&psrc2, g_src2);
    cudaGetSymbolAddress((void**)&py,    g_y);
    cudaGetSymbolAddress((void**)&pxh,   g_xh);
    cudaGetSymbolAddress((void**)&pxl,   g_xl);
    cudaGetSymbolAddress((void**)&pyh,   g_yh);
    cudaGetSymbolAddress((void**)&pyl,   g_yl);
    cudaGetSymbolAddress((void**)&patth, g_atth);
    cudaGetSymbolAddress((void**)&pattl, g_attl);
    cudaGetSymbolAddress((void**)&phh,   g_hh);
    cudaGetSymbolAddress((void**)&phl,   g_hl);
    cudaGetSymbolAddress((void**)&pw3h,  g_w3h);
    cudaGetSymbolAddress((void**)&pw3l,  g_w3l);
    cudaGetSymbolAddress((void**)&ppwh,  g_pwh);
    cudaGetSymbolAddress((void**)&ppwl,  g_pwl);
    cudaGetSymbolAddress((void**)&pf1h,  g_f1h);
    cudaGetSymbolAddress((void**)&pf1l,  g_f1l);
    cudaGetSymbolAddress((void**)&pf2h,  g_f2h);
    cudaGetSymbolAddress((void**)&pf2l,  g_f2l);

    cudaFuncSetAttribute(gemm_mma<false,false,true,false>, cudaFuncAttributeMaxDynamicSharedMemorySize, GEMM_SMEM);
    cudaFuncSetAttribute(gemm_mma<true, false,true,false>, cudaFuncAttributeMaxDynamicSharedMemorySize, GEMM_SMEM);
    cudaFuncSetAttribute(gemm_mma<false,true, false,true>, cudaFuncAttributeMaxDynamicSharedMemorySize, GEMM_SMEM);

    // weight prep (transpose + hi/lo split)
    wsplit_qkv_kernel<<<(3*D*D + 255)/256, 256>>>(Wq, Wk, Wv);
    wsplit_kernel<<<(D*D + 255)/256, 256>>>(proj_w, ppwh, ppwl, D, D);
    wsplit_kernel<<<(D*FF + 255)/256, 256>>>(ff_w1, pf1h, pf1l, D, FF);
    wsplit_kernel<<<(FF*D + 255)/256, 256>>>(ff_w2, pf2h, pf2l, FF, D);

    // x = rmsnorm(src)  (+ hi/lo)
    rmsnorm_kernel<<<BT, 128>>>(src, norm_w, px, pxh, pxl);

    // q,k,v = x @ W + b   (N layout [bt][h*64+c])
    dim3 g1(D / 128, BT / 128);   // (4, 32)
    gemm_mma<false,false,true,false><<<g1, 256, GEMM_SMEM>>>(pxh, pxl, pw3h,         pw3l,         bq, nullptr, pq, nullptr, nullptr, BT, D, D);
    gemm_mma<false,false,true,false><<<g1, 256, GEMM_SMEM>>>(pxh, pxl, pw3h + D*D,   pw3l + D*D,   bk, nullptr, pk, nullptr, nullptr, BT, D, D);
    gemm_mma<false,false,true,false><<<g1, 256, GEMM_SMEM>>>(pxh, pxl, pw3h + 2*D*D, pw3l + 2*D*D, bv, nullptr, pv, nullptr, nullptr, BT, D, D);

    // fused attention -> att (hi/lo)
    attn_kernel<<<dim3(T, H), 256>>>(relp);

    // src2 = x + att @ proj_w + proj_b
    gemm_mma<true,false,true,false><<<g1, 256, GEMM_SMEM>>>(patth, pattl, ppwh, ppwl, proj_b, px, psrc2, nullptr, nullptr, BT, D, D);

    // y = rmsnorm(src2) (+ hi/lo)
    rmsnorm_kernel<<<BT, 128>>>(psrc2, norm_w, py, pyh, pyl);

    // h = gelu(y @ ff_w1 + ff_b1)  -> hi/lo only
    dim3 g2(FF / 128, BT / 128);  // (16, 32)
    gemm_mma<false,true,false,true><<<g2, 256, GEMM_SMEM>>>(pyh, pyl, pf1h, pf1l, ff_b1, nullptr, nullptr, phh, phl, BT, FF, D);

    // out = y + h @ ff_w2 + ff_b2
    gemm_mma<true,false,true,false><<<g1, 256, GEMM_SMEM>>>(phh, phl, pf2h, pf2l, ff_b2, py, out, nullptr, nullptr, BT, D, FF);
}

// round 5
// speedup vs baseline: 3.2396x; 2.5414x over previous
#include <cuda_runtime.h>
#include <cuda_bf16.h>
#include <math.h>
#include <stdint.h>

#define BATCH 8
#define T 512
#define D 512
#define H 8
#define HS 64
#define BT (BATCH*T)     // 4096
#define FF 2048

// ===================== device scratch =====================
__device__ __align__(16) float g_x[BT*D];
__device__ __align__(16) float g_q[BT*D];            // fp32 q (rel kernel)
__device__ __align__(16) float g_src2[BT*D];
__device__ __align__(16) float g_y[BT*D];
__device__ __align__(16) float g_scores[BATCH*H*T*T];        // 64MB
__device__ __align__(16) __nv_bfloat16 g_ph[BATCH*H*T*T];    // probs hi
__device__ __align__(16) __nv_bfloat16 g_pl[BATCH*H*T*T];    // probs lo
__device__ __align__(16) __nv_bfloat16 g_xh[BT*D],  g_xl[BT*D];
__device__ __align__(16) __nv_bfloat16 g_yh[BT*D],  g_yl[BT*D];
__device__ __align__(16) __nv_bfloat16 g_qh[BT*D],  g_ql[BT*D];
__device__ __align__(16) __nv_bfloat16 g_k8h[BT*D], g_k8l[BT*D];     // 8*k hi/lo
__device__ __align__(16) __nv_bfloat16 g_vth[BATCH*H*HS*T], g_vtl[BATCH*H*HS*T]; // v transposed [bh][c][t]
__device__ __align__(16) __nv_bfloat16 g_atth[BT*D], g_attl[BT*D];
__device__ __align__(16) __nv_bfloat16 g_hh[BT*FF], g_hl[BT*FF];
__device__ __align__(16) __nv_bfloat16 g_w3h[3*D*D], g_w3l[3*D*D];   // [mat][n][k]
__device__ __align__(16) __nv_bfloat16 g_pwh[D*D],  g_pwl[D*D];      // [n][k]
__device__ __align__(16) __nv_bfloat16 g_f1h[FF*D], g_f1l[FF*D];
__device__ __align__(16) __nv_bfloat16 g_f2h[D*FF], g_f2l[D*FF];
__device__ __align__(16) float g_zero[2048];

__device__ __forceinline__ void split2(float v, __nv_bfloat16& h, __nv_bfloat16& l) {
    h = __float2bfloat16(v);
    l = __float2bfloat16(v - __bfloat162float(h));
}

// ===================== warp-MMA primitives =====================
__device__ __forceinline__ void mma_bf16(float* d, const uint32_t* a, const uint32_t* b) {
    asm volatile(
        "mma.sync.aligned.m16n8k16.row.col.f32.bf16.bf16.f32 "
        "{%0,%1,%2,%3}, {%4,%5,%6,%7}, {%8,%9}, {%0,%1,%2,%3};"
        : "+f"(d[0]), "+f"(d[1]), "+f"(d[2]), "+f"(d[3])
        : "r"(a[0]), "r"(a[1]), "r"(a[2]), "r"(a[3]), "r"(b[0]), "r"(b[1]));
}
__device__ __forceinline__ void ldsm4(uint32_t* r, uint32_t addr) {
    asm volatile("ldmatrix.sync.aligned.m8n8.x4.shared.b16 {%0,%1,%2,%3}, [%4];"
        : "=r"(r[0]), "=r"(r[1]), "=r"(r[2]), "=r"(r[3]) : "r"(addr));
}
__device__ __forceinline__ uint32_t smem_to_u32(const void* p) {
    uint32_t a;
    asm("{ .reg .u64 t; cvta.to.shared.u64 t, %1; cvt.u32.u64 %0, t; }" : "=r"(a) : "l"(p));
    return a;
}

// ===================== weight prep =====================
__global__ void wsplit_kernel(const float* __restrict__ W,
                              __nv_bfloat16* __restrict__ Wh, __nv_bfloat16* __restrict__ Wl,
                              int K, int N)
{
    int idx = blockIdx.x * 256 + threadIdx.x;
    if (idx >= K * N) return;
    int n = idx / K, k = idx % K;
    float v = W[(size_t)k * N + n];
    __nv_bfloat16 h, l; split2(v, h, l);
    Wh[idx] = h; Wl[idx] = l;
}

__global__ void wsplit_qkv_kernel(const float* __restrict__ Wq,
                                  const float* __restrict__ Wk,
                                  const float* __restrict__ Wv)
{
    int idx = blockIdx.x * 256 + threadIdx.x;
    if (idx >= 3 * D * D) return;
    int mat = idx / (D * D);
    int r   = idx % (D * D);
    int n = r / D, k = r % D;
    const float* W = (mat == 0) ? Wq : (mat == 1) ? Wk : Wv;
    float v = W[(((size_t)(n >> 6)) * D + k) * HS + (n & 63)];
    __nv_bfloat16 h, l; split2(v, h, l);
    g_w3h[idx] = h; g_w3l[idx] = l;
}

// ===================== rmsnorm =====================
__global__ __launch_bounds__(128) void rmsnorm_kernel(
    const float* __restrict__ in, const float* __restrict__ w,
    float* __restrict__ out, __nv_bfloat16* __restrict__ outh, __nv_bfloat16* __restrict__ outl)
{
    int row = blockIdx.x;
    int tid = threadIdx.x;
    const float4 v = ((const float4*)(in + (size_t)row * D))[tid];
    float ss = v.x*v.x + v.y*v.y + v.z*v.z + v.w*v.w;
    #pragma unroll
    for (int o = 16; o > 0; o >>= 1) ss += __shfl_xor_sync(0xffffffffu, ss, o);
    __shared__ float ws[4];
    if ((tid & 31) == 0) ws[tid >> 5] = ss;
    __syncthreads();
    float total = ws[0] + ws[1] + ws[2] + ws[3];
    float r = rsqrtf(total * (1.0f / (float)D) + 1e-6f);
    const float4 wv = ((const float4*)w)[tid];
    float4 o;
    o.x = v.x * r * wv.x; o.y = v.y * r * wv.y;
    o.z = v.z * r * wv.z; o.w = v.w * r * wv.w;
    ((float4*)(out + (size_t)row * D))[tid] = o;
    __nv_bfloat16 h0,l0,h1,l1,h2,l2,h3,l3;
    split2(o.x,h0,l0); split2(o.y,h1,l1); split2(o.z,h2,l2); split2(o.w,h3,l3);
    __nv_bfloat162 hA; hA.x=h0; hA.y=h1;
    __nv_bfloat162 hB; hB.x=h2; hB.y=h3;
    __nv_bfloat162 lA; lA.x=l0; lA.y=l1;
    __nv_bfloat162 lB; lB.x=l2; lB.y=l3;
    size_t base = (size_t)row * D + tid * 4;
    *(__nv_bfloat162*)(outh + base)     = hA;
    *(__nv_bfloat162*)(outh + base + 2) = hB;
    *(__nv_bfloat162*)(outl + base)     = lA;
    *(__nv_bfloat162*)(outl + base + 2) = lB;
}

// ===================== warp-MMA split-bf16 GEMM ============================
static constexpr int TROW   = 80;
static constexpr int TILEB  = 128 * TROW;    // 10240
static constexpr int STAGEB = 4 * TILEB;     // 40960
static constexpr int GEMM_SMEM = 2 * STAGEB; // 81920

// OUTT: write C transposed hi/lo as v_t[(b*H+h)*HS+c][T] (v GEMM only)
template<bool RESID, bool GELU, bool OUTF, bool OUTS, bool OUTT>
__global__ __launch_bounds__(256, 1) void gemm_mma(
    const __nv_bfloat16* __restrict__ Ah, const __nv_bfloat16* __restrict__ Al,
    const __nv_bfloat16* __restrict__ Bh, const __nv_bfloat16* __restrict__ Bl,
    const float* __restrict__ bias, const float* __restrict__ R,
    float* __restrict__ C, __nv_bfloat16* __restrict__ Ch, __nv_bfloat16* __restrict__ Cl,
    int M, int N, int K, int lda, int ldb, int ldc, float osc)
{
    extern __shared__ char sm[];
    const int tid  = threadIdx.x;
    const int wid  = tid >> 5, lane = tid & 31;
    const int warpM = wid & 1, warpN = wid >> 1;
    const int bm = blockIdx.y * 128, bn = blockIdx.x * 128;
    const uint32_t smb = smem_to_u32(sm);

    const int lrow   = tid >> 2;
    const int lchunk = tid & 3;
    const int soff   = lrow * TROW + lchunk * 16;

    const int a_off = (warpM * 64 + (lane & 15)) * TROW + (lane >> 4) * 16;
    const int b_off = (warpN * 32 + ((lane >> 4) << 3) + (lane & 7)) * TROW + ((lane >> 3) & 1) * 16;

    float acc[4][4][4];
    #pragma unroll
    for (int i = 0; i < 4; i++)
        #pragma unroll
        for (int j = 0; j < 4; j++)
            #pragma unroll
            for (int r = 0; r < 4; r++) acc[i][j][r] = 0.f;

    const int nch = K >> 5;
    uint4 pf[8];

    auto ldg = [&](int c) {
        const int k0 = c << 5;
        const __nv_bfloat16* pa  = Ah + (size_t)(bm + lrow) * lda + k0 + lchunk * 8;
        const __nv_bfloat16* pal = Al + (size_t)(bm + lrow) * lda + k0 + lchunk * 8;
        const __nv_bfloat16* pb  = Bh + (size_t)(bn + lrow) * ldb + k0 + lchunk * 8;
        const __nv_bfloat16* pbl = Bl + (size_t)(bn + lrow) * ldb + k0 + lchunk * 8;
        pf[0] = *(const uint4*)pa;
        pf[1] = *(const uint4*)(pa + (size_t)64 * lda);
        pf[2] = *(const uint4*)pal;
        pf[3] = *(const uint4*)(pal + (size_t)64 * lda);
        pf[4] = *(const uint4*)pb;
        pf[5] = *(const uint4*)(pb + (size_t)64 * ldb);
        pf[6] = *(const uint4*)pbl;
        pf[7] = *(const uint4*)(pbl + (size_t)64 * ldb);
    };

    ldg(0);
    int p = 0;
    for (int c = 0; c < nch; ++c) {
        char* st = sm + p * STAGEB;
        *(uint4*)(st + soff)                       = pf[0];
        *(uint4*)(st + soff + 64 * TROW)           = pf[1];
        *(uint4*)(st + TILEB   + soff)             = pf[2];
        *(uint4*)(st + TILEB   + soff + 64 * TROW) = pf[3];
        *(uint4*)(st + 2*TILEB + soff)             = pf[4];
        *(uint4*)(st + 2*TILEB + soff + 64 * TROW) = pf[5];
        *(uint4*)(st + 3*TILEB + soff)             = pf[6];
        *(uint4*)(st + 3*TILEB + soff + 64 * TROW) = pf[7];
        __syncthreads();
        if (c + 1 < nch) ldg(c + 1);

        const uint32_t sb = smb + p * STAGEB;
        #pragma unroll
        for (int ks = 0; ks < 2; ++ks) {
            uint32_t ahr[4][4], alr[4][4], bhr[2][4], blr[2][4];
            #pragma unroll
            for (int i = 0; i < 4; ++i) {
                ldsm4(ahr[i], sb + a_off + i * (16 * TROW) + ks * 32);
                ldsm4(alr[i], sb + TILEB + a_off + i * (16 * TROW) + ks * 32);
            }
            #pragma unroll
            for (int j = 0; j < 2; ++j) {
                ldsm4(bhr[j], sb + 2*TILEB + b_off + j * (16 * TROW) + ks * 32);
                ldsm4(blr[j], sb + 3*TILEB + b_off + j * (16 * TROW) + ks * 32);
            }
            #pragma unroll
            for (int i = 0; i < 4; ++i)
                #pragma unroll
                for (int j = 0; j < 4; ++j) {
                    uint32_t bfh[2] = { bhr[j >> 1][(j & 1) * 2], bhr[j >> 1][(j & 1) * 2 + 1] };
                    uint32_t bfl[2] = { blr[j >> 1][(j & 1) * 2], blr[j >> 1][(j & 1) * 2 + 1] };
                    mma_bf16(acc[i][j], ahr[i], bfh);
                    mma_bf16(acc[i][j], ahr[i], bfl);
                    mma_bf16(acc[i][j], alr[i], bfh);
                }
        }
        p ^= 1;
    }

    #pragma unroll
    for (int i = 0; i < 4; ++i) {
        const int m0 = bm + warpM * 64 + i * 16 + (lane >> 2);
        #pragma unroll
        for (int j = 0; j < 4; ++j) {
            const int n = bn + warpN * 32 + j * 8 + (lane & 3) * 2;
            const float b0 = bias[n], b1 = bias[n + 1];
            #pragma unroll
            for (int rr = 0; rr < 2; ++rr) {
                const int m = m0 + rr * 8;
                float v0 = acc[i][j][rr * 2 + 0] + b0;
                float v1 = acc[i][j][rr * 2 + 1] + b1;
                if (RESID) {
                    const float2 rv = *(const float2*)(R + (size_t)m * ldc + n);
                    v0 += rv.x; v1 += rv.y;
                }
                v0 *= osc; v1 *= osc;
                if (GELU) {
                    v0 = 0.5f * v0 * (1.f + erff(v0 * 0.70710678118654752f));
                    v1 = 0.5f * v1 * (1.f + erff(v1 * 0.70710678118654752f));
                }
                if (OUTF) {
                    float2 o; o.x = v0; o.y = v1;
                    *(float2*)(C + (size_t)m * ldc + n) = o;
                }
                if (OUTS) {
                    __nv_bfloat16 h0, l0, h1, l1;
                    split2(v0, h0, l0); split2(v1, h1, l1);
                    __nv_bfloat162 hv; hv.x = h0; hv.y = h1;
                    __nv_bfloat162 lv; lv.x = l0; lv.y = l1;
                    *(__nv_bfloat162*)(Ch + (size_t)m * ldc + n) = hv;
                    *(__nv_bfloat162*)(Cl + (size_t)m * ldc + n) = lv;
                }
                if (OUTT) {
                    // m = b*T + t, n = h*HS + c  ->  vt[(b*H+h)*HS+c][t]
                    const int bb = m >> 9, tt = m & (T - 1);
                    const int hh = n >> 6, cc = n & (HS - 1);
                    __nv_bfloat16 h0, l0, h1, l1;
                    split2(v0, h0, l0); split2(v1, h1, l1);
                    size_t o0 = (((size_t)bb * H + hh) * HS + cc) * T + tt;
                    Ch[o0] = h0; Cl[o0] = l0;
                    Ch[o0 + T] = h1; Cl[o0 + T] = l1;
                }
            }
        }
    }
}

// ===================== rel kernel: R[b,h,t,v] = q . rel =====================
__global__ __launch_bounds__(256) void rel_kernel(const float* __restrict__ relp)
{
    const int t = blockIdx.x;
    const int h = blockIdx.y;
    const int tid = threadIdx.x;

    __shared__ float4 qs4[8 * 16];
    if (tid < 128) {
        int b = tid >> 4, c4 = tid & 15;
        qs4[tid] = *(const float4*)(g_q + ((size_t)(b * T + t)) * D + h * HS + c4 * 4);
    }
    __syncthreads();

    #pragma unroll
    for (int i = 0; i < 2; i++) {
        const int v = tid + i * 256;
        const float4* rel4 = (const float4*)(relp + (((size_t)h * T + t) * T + v) * HS);
        float acc[8];
        #pragma unroll
        for (int b = 0; b < 8; b++) acc[b] = 0.f;
        #pragma unroll 2
        for (int c4 = 0; c4 < 16; c4++) {
            float4 r = rel4[c4];
            #pragma unroll
            for (int b = 0; b < 8; b++) {
                float4 q = qs4[b * 16 + c4];
                acc[b] = fmaf(q.x, r.x, acc[b]);
                acc[b] = fmaf(q.y, r.y, acc[b]);
                acc[b] = fmaf(q.z, r.z, acc[b]);
                acc[b] = fmaf(q.w, r.w, acc[b]);
            }
        }
        #pragma unroll
        for (int b = 0; b < 8; b++)
            g_scores[(((size_t)(b * H + h)) * T + t) * T + v] = acc[b];
    }
}

// ===================== qk kernel: scores += q @ (8k)^T (MMA) ================
__global__ __launch_bounds__(256, 1) void qk_kernel()
{
    extern __shared__ char sm[];
    const int tid  = threadIdx.x;
    const int wid  = tid >> 5, lane = tid & 31;
    const int warpM = wid & 1, warpN = wid >> 1;
    const int bh = blockIdx.z;
    const int b = bh >> 3, h = bh & 7;
    const int bm = blockIdx.y * 128, bn = blockIdx.x * 128;
    const uint32_t smb = smem_to_u32(sm);

    const __nv_bfloat16* Ah = g_qh  + (size_t)(b * T) * D + h * HS;
    const __nv_bfloat16* Al = g_ql  + (size_t)(b * T) * D + h * HS;
    const __nv_bfloat16* Bh = g_k8h + (size_t)(b * T) * D + h * HS;
    const __nv_bfloat16* Bl = g_k8l + (size_t)(b * T) * D + h * HS;

    const int lrow   = tid >> 2;
    const int lchunk = tid & 3;
    const int soff   = lrow * TROW + lchunk * 16;
    const int a_off = (warpM * 64 + (lane & 15)) * TROW + (lane >> 4) * 16;
    const int b_off = (warpN * 32 + ((lane >> 4) << 3) + (lane & 7)) * TROW + ((lane >> 3) & 1) * 16;

    float acc[4][4][4];
    #pragma unroll
    for (int i = 0; i < 4; i++)
        #pragma unroll
        for (int j = 0; j < 4; j++)
            #pragma unroll
            for (int r = 0; r < 4; r++) acc[i][j][r] = 0.f;

    // load both K-chunks (K=64) into two stages, one sync
    #pragma unroll
    for (int c = 0; c < 2; ++c) {
        char* st = sm + c * STAGEB;
        const int k0 = c << 5;
        *(uint4*)(st + soff)                       = *(const uint4*)(Ah + (size_t)(bm + lrow) * D + k0 + lchunk * 8);
        *(uint4*)(st + soff + 64 * TROW)           = *(const uint4*)(Ah + (size_t)(bm + lrow + 64) * D + k0 + lchunk * 8);
        *(uint4*)(st + TILEB   + soff)             = *(const uint4*)(Al + (size_t)(bm + lrow) * D + k0 + lchunk * 8);
        *(uint4*)(st + TILEB   + soff + 64 * TROW) = *(const uint4*)(Al + (size_t)(bm + lrow + 64) * D + k0 + lchunk * 8);
        *(uint4*)(st + 2*TILEB + soff)             = *(const uint4*)(Bh + (size_t)(bn + lrow) * D + k0 + lchunk * 8);
        *(uint4*)(st + 2*TILEB + soff + 64 * TROW) = *(const uint4*)(Bh + (size_t)(bn + lrow + 64) * D + k0 + lchunk * 8);
        *(uint4*)(st + 3*TILEB + soff)             = *(const uint4*)(Bl + (size_t)(bn + lrow) * D + k0 + lchunk * 8);
        *(uint4*)(st + 3*TILEB + soff + 64 * TROW) = *(const uint4*)(Bl + (size_t)(bn + lrow + 64) * D + k0 + lchunk * 8);
    }
    __syncthreads();

    #pragma unroll
    for (int c = 0; c < 2; ++c) {
        const uint32_t sb = smb + c * STAGEB;
        #pragma unroll
        for (int ks = 0; ks < 2; ++ks) {
            uint32_t ahr[4][4], alr[4][4], bhr[2][4], blr[2][4];
            #pragma unroll
            for (int i = 0; i < 4; ++i) {
                ldsm4(ahr[i], sb + a_off + i * (16 * TROW) + ks * 32);
                ldsm4(alr[i], sb + TILEB + a_off + i * (16 * TROW) + ks * 32);
            }
            #pragma unroll
            for (int j = 0; j < 2; ++j) {
                ldsm4(bhr[j], sb + 2*TILEB + b_off + j * (16 * TROW) + ks * 32);
                ldsm4(blr[j], sb + 3*TILEB + b_off + j * (16 * TROW) + ks * 32);
            }
            #pragma unroll
            for (int i = 0; i < 4; ++i)
                #pragma unroll
                for (int j = 0; j < 4; ++j) {
                    uint32_t bfh[2] = { bhr[j >> 1][(j & 1) * 2], bhr[j >> 1][(j & 1) * 2 + 1] };
                    uint32_t bfl[2] = { blr[j >> 1][(j & 1) * 2], blr[j >> 1][(j & 1) * 2 + 1] };
                    mma_bf16(acc[i][j], ahr[i], bfh);
                    mma_bf16(acc[i][j], ahr[i], bfl);
                    mma_bf16(acc[i][j], alr[i], bfh);
                }
        }
    }

    float* Cb = g_scores + (size_t)bh * T * T;
    #pragma unroll
    for (int i = 0; i < 4; ++i) {
        const int m0 = bm + warpM * 64 + i * 16 + (lane >> 2);
        #pragma unroll
        for (int j = 0; j < 4; ++j) {
            const int n = bn + warpN * 32 + j * 8 + (lane & 3) * 2;
            #pragma unroll
            for (int rr = 0; rr < 2; ++rr) {
                const int m = m0 + rr * 8;
                float2 rv = *(const float2*)(Cb + (size_t)m * T + n);
                float2 o;
                o.x = acc[i][j][rr * 2 + 0] + rv.x;
                o.y = acc[i][j][rr * 2 + 1] + rv.y;
                *(float2*)(Cb + (size_t)m * T + n) = o;
            }
        }
    }
}

// ===================== softmax: warp per row -> probs hi/lo ================
__global__ __launch_bounds__(256) void softmax_kernel()
{
    const int r = blockIdx.x * 8 + (threadIdx.x >> 5);
    const int lane = threadIdx.x & 31;
    const float* row = g_scores + (size_t)r * T;

    float4 v[4];
    float m = -1e30f;
    #pragma unroll
    for (int j = 0; j < 4; ++j) {
        v[j] = ((const float4*)row)[lane + 32 * j];
        m = fmaxf(m, fmaxf(fmaxf(v[j].x, v[j].y), fmaxf(v[j].z, v[j].w)));
    }
    #pragma unroll
    for (int o = 16; o > 0; o >>= 1) m = fmaxf(m, __shfl_xor_sync(0xffffffffu, m, o));
    float s = 0.f;
    #pragma unroll
    for (int j = 0; j < 4; ++j) {
        v[j].x = __expf(v[j].x - m); v[j].y = __expf(v[j].y - m);
        v[j].z = __expf(v[j].z - m); v[j].w = __expf(v[j].w - m);
        s += v[j].x + v[j].y + v[j].z + v[j].w;
    }
    #pragma unroll
    for (int o = 16; o > 0; o >>= 1) s += __shfl_xor_sync(0xffffffffu, s, o);
    const float inv = 1.f / s;
    #pragma unroll
    for (int j = 0; j < 4; ++j) {
        float p0 = v[j].x * inv, p1 = v[j].y * inv, p2 = v[j].z * inv, p3 = v[j].w * inv;
        __nv_bfloat16 h0,l0,h1,l1,h2,l2,h3,l3;
        split2(p0,h0,l0); split2(p1,h1,l1); split2(p2,h2,l2); split2(p3,h3,l3);
        __nv_bfloat162 hA; hA.x=h0; hA.y=h1;
        __nv_bfloat162 hB; hB.x=h2; hB.y=h3;
        __nv_bfloat162 lA; lA.x=l0; lA.y=l1;
        __nv_bfloat162 lB; lB.x=l2; lB.y=l3;
        size_t base = (size_t)r * T + (lane + 32 * j) * 4;
        *(__nv_bfloat162*)(g_ph + base)     = hA;
        *(__nv_bfloat162*)(g_ph + base + 2) = hB;
        *(__nv_bfloat162*)(g_pl + base)     = lA;
        *(__nv_bfloat162*)(g_pl + base + 2) = lB;
    }
}

// ===================== AV kernel: out = P @ V (MMA) =========================
static constexpr int AV_PB   = 128 * TROW;   // 10240
static constexpr int AV_VB   = 64 * TROW;    // 5120
static constexpr int AV_STG  = 2 * AV_PB + 2 * AV_VB;  // 30720
static constexpr int AV_SMEM = 2 * AV_STG;             // 61440

__global__ __launch_bounds__(256, 1) void av_kernel()
{
    extern __shared__ char sm[];
    const int tid  = threadIdx.x;
    const int wid  = tid >> 5, lane = tid & 31;
    const int warpM = wid & 3, warpN = wid >> 2;
    const int bh = blockIdx.y;
    const int b = bh >> 3, h = bh & 7;
    const int t0 = blockIdx.x * 128;
    const uint32_t smb = smem_to_u32(sm);

    const __nv_bfloat16* Ph = g_ph  + ((size_t)bh * T + t0) * T;
    const __nv_bfloat16* Pl = g_pl  + ((size_t)bh * T + t0) * T;
    const __nv_bfloat16* Vh = g_vth + (size_t)bh * HS * T;
    const __nv_bfloat16* Vl = g_vtl + (size_t)bh * HS * T;

    const int lrow   = tid >> 2;
    const int lchunk = tid & 3;
    const int soff   = lrow * TROW + lchunk * 16;
    const int a_off = (warpM * 32 + (lane & 15)) * TROW + (lane >> 4) * 16;
    const int b_off = (warpN * 32 + ((lane >> 4) << 3) + (lane & 7)) * TROW + ((lane >> 3) & 1) * 16;

    float acc[2][4][4];
    #pragma unroll
    for (int i = 0; i < 2; i++)
        #pragma unroll
        for (int j = 0; j < 4; j++)
            #pragma unroll
            for (int r = 0; r < 4; r++) acc[i][j][r] = 0.f;

    uint4 pf[6];
    auto ldg = [&](int c) {
        const int k0 = c << 5;
        pf[0] = *(const uint4*)(Ph + (size_t)lrow * T + k0 + lchunk * 8);
        pf[1] = *(const uint4*)(Ph + (size_t)(lrow + 64) * T + k0 + lchunk * 8);
        pf[2] = *(const uint4*)(Pl + (size_t)lrow * T + k0 + lchunk * 8);
        pf[3] = *(const uint4*)(Pl + (size_t)(lrow + 64) * T + k0 + lchunk * 8);
        pf[4] = *(const uint4*)(Vh + (size_t)lrow * T + k0 + lchunk * 8);
        pf[5] = *(const uint4*)(Vl + (size_t)lrow * T + k0 + lchunk * 8);
    };

    ldg(0);
    int p = 0;
    const int nch = T >> 5;  // 16
    for (int c = 0; c < nch; ++c) {
        char* st = sm + p * AV_STG;
        *(uint4*)(st + soff)                     = pf[0];
        *(uint4*)(st + soff + 64 * TROW)         = pf[1];
        *(uint4*)(st + AV_PB + soff)             = pf[2];
        *(uint4*)(st + AV_PB + soff + 64 * TROW) = pf[3];
        *(uint4*)(st + 2*AV_PB + soff)           = pf[4];
        *(uint4*)(st + 2*AV_PB + AV_VB + soff)   = pf[5];
        __syncthreads();
        if (c + 1 < nch) ldg(c + 1);

        const uint32_t sb = smb + p * AV_STG;
        #pragma unroll
        for (int ks = 0; ks < 2; ++ks) {
            uint32_t ahr[2][4], alr[2][4], bhr[2][4], blr[2][4];
            #pragma unroll
            for (int i = 0; i < 2; ++i) {
                ldsm4(ahr[i], sb + a_off + i * (16 * TROW) + ks * 32);
                ldsm4(alr[i], sb + AV_PB + a_off + i * (16 * TROW) + ks * 32);
            }
            #pragma unroll
            for (int j = 0; j < 2; ++j) {
                ldsm4(bhr[j], sb + 2*AV_PB + b_off + j * (16 * TROW) + ks * 32);
                ldsm4(blr[j], sb + 2*AV_PB + AV_VB + b_off + j * (16 * TROW) + ks * 32);
            }
            #pragma unroll
            for (int i = 0; i < 2; ++i)
                #pragma unroll
                for (int j = 0; j < 4; ++j) {
                    uint32_t bfh[2] = { bhr[j >> 1][(j & 1) * 2], bhr[j >> 1][(j & 1) * 2 + 1] };
                    uint32_t bfl[2] = { blr[j >> 1][(j & 1) * 2], blr[j >> 1][(j & 1) * 2 + 1] };
                    mma_bf16(acc[i][j], ahr[i], bfh);
                    mma_bf16(acc[i][j], ahr[i], bfl);
                    mma_bf16(acc[i][j], alr[i], bfh);
                }
        }
        p ^= 1;
    }

    #pragma unroll
    for (int i = 0; i < 2; ++i) {
        #pragma unroll
        for (int j = 0; j < 4; ++j) {
            const int cc = warpN * 32 + j * 8 + (lane & 3) * 2;
            #pragma unroll
            for (int rr = 0; rr < 2; ++rr) {
                const int m = t0 + warpM * 32 + i * 16 + (lane >> 2) + rr * 8;
                float v0 = acc[i][j][rr * 2 + 0];
                float v1 = acc[i][j][rr * 2 + 1];
                __nv_bfloat16 h0, l0, h1, l1;
                split2(v0, h0, l0); split2(v1, h1, l1);
                __nv_bfloat162 hv; hv.x = h0; hv.y = h1;
                __nv_bfloat162 lv; lv.x = l0; lv.y = l1;
                size_t off = ((size_t)(b * T + m)) * D + h * HS + cc;
                *(__nv_bfloat162*)(g_atth + off) = hv;
                *(__nv_bfloat162*)(g_attl + off) = lv;
            }
        }
    }
}

// ===================== launch ==============================================
extern "C" void kernel_launch(void* const* d_in, const int* in_sizes, int n_in,
                              void* d_out, int out_size)
{
    (void)in_sizes; (void)n_in; (void)out_size;
    const float* src    = (const float*)d_in[0];
    const float* norm_w = (const float*)d_in[1];
    const float* Wq     = (const float*)d_in[2];
    const float* bq     = (const float*)d_in[3];
    const float* Wk     = (const float*)d_in[4];
    const float* bk     = (const float*)d_in[5];
    const float* Wv     = (const float*)d_in[6];
    const float* bv     = (const float*)d_in[7];
    const float* relp   = (const float*)d_in[8];
    const float* proj_w = (const float*)d_in[9];
    const float* proj_b = (const float*)d_in[10];
    const float* ff_w1  = (const float*)d_in[11];
    const float* ff_b1  = (const float*)d_in[12];
    const float* ff_w2  = (const float*)d_in[13];
    const float* ff_b2  = (const float*)d_in[14];
    float* out = (float*)d_out;

    float *px, *pq, *psrc2, *py;
    __nv_bfloat16 *pxh, *pxl, *pyh, *pyl, *pqh, *pql, *pk8h, *pk8l, *pvth, *pvtl;
    __nv_bfloat16 *patth, *pattl, *phh, *phl;
    __nv_bfloat16 *pw3h, *pw3l, *ppwh, *ppwl, *pf1h, *pf1l, *pf2h, *pf2l;
    cudaGetSymbolAddress((void**)&px,    g_x);
    cudaGetSymbolAddress((void**)&pq,    g_q);
    cudaGetSymbolAddress((void**)&psrc2, g_src2);
    cudaGetSymbolAddress((void**)&py,    g_y);
    cudaGetSymbolAddress((void**)&pxh,   g_xh);
    cudaGetSymbolAddress((void**)&pxl,   g_xl);
    cudaGetSymbolAddress((void**)&pyh,   g_yh);
    cudaGetSymbolAddress((void**)&pyl,   g_yl);
    cudaGetSymbolAddress((void**)&pqh,   g_qh);
    cudaGetSymbolAddress((void**)&pql,   g_ql);
    cudaGetSymbolAddress((void**)&pk8h,  g_k8h);
    cudaGetSymbolAddress((void**)&pk8l,  g_k8l);
    cudaGetSymbolAddress((void**)&pvth,  g_vth);
    cudaGetSymbolAddress((void**)&pvtl,  g_vtl);
    cudaGetSymbolAddress((void**)&patth, g_atth);
    cudaGetSymbolAddress((void**)&pattl, g_attl);
    cudaGetSymbolAddress((void**)&phh,   g_hh);
    cudaGetSymbolAddress((void**)&phl,   g_hl);
    cudaGetSymbolAddress((void**)&pw3h,  g_w3h);
    cudaGetSymbolAddress((void**)&pw3l,  g_w3l);
    cudaGetSymbolAddress((void**)&ppwh,  g_pwh);
    cudaGetSymbolAddress((void**)&ppwl,  g_pwl);
    cudaGetSymbolAddress((void**)&pf1h,  g_f1h);
    cudaGetSymbolAddress((void**)&pf1l,  g_f1l);
    cudaGetSymbolAddress((void**)&pf2h,  g_f2h);
    cudaGetSymbolAddress((void**)&pf2l,  g_f2l);
    float* pzero; cudaGetSymbolAddress((void**)&pzero, g_zero);

    cudaFuncSetAttribute(gemm_mma<false,false,true,true,false>,  cudaFuncAttributeMaxDynamicSharedMemorySize, GEMM_SMEM);
    cudaFuncSetAttribute(gemm_mma<false,false,false,true,false>, cudaFuncAttributeMaxDynamicSharedMemorySize, GEMM_SMEM);
    cudaFuncSetAttribute(gemm_mma<false,false,false,false,true>, cudaFuncAttributeMaxDynamicSharedMemorySize, GEMM_SMEM);
    cudaFuncSetAttribute(gemm_mma<true, false,true,false,false>, cudaFuncAttributeMaxDynamicSharedMemorySize, GEMM_SMEM);
    cudaFuncSetAttribute(gemm_mma<false,true, false,true,false>, cudaFuncAttributeMaxDynamicSharedMemorySize, GEMM_SMEM);
    cudaFuncSetAttribute(qk_kernel, cudaFuncAttributeMaxDynamicSharedMemorySize, GEMM_SMEM);
    cudaFuncSetAttribute(av_kernel, cudaFuncAttributeMaxDynamicSharedMemorySize, AV_SMEM);

    // weight prep
    wsplit_qkv_kernel<<<(3*D*D + 255)/256, 256>>>(Wq, Wk, Wv);
    wsplit_kernel<<<(D*D + 255)/256, 256>>>(proj_w, ppwh, ppwl, D, D);
    wsplit_kernel<<<(D*FF + 255)/256, 256>>>(ff_w1, pf1h, pf1l, D, FF);
    wsplit_kernel<<<(FF*D + 255)/256, 256>>>(ff_w2, pf2h, pf2l, FF, D);

    // x = rmsnorm(src)
    rmsnorm_kernel<<<BT, 128>>>(src, norm_w, px, pxh, pxl);

    dim3 g1(D / 128, BT / 128);   // (4, 32)
    // q: fp32 + hi/lo
    gemm_mma<false,false,true,true,false><<<g1, 256, GEMM_SMEM>>>(pxh, pxl, pw3h, pw3l, bq, nullptr, pq, pqh, pql, BT, D, D, D, D, D, 1.f);
    // k: hi/lo scaled by 8
    gemm_mma<false,false,false,true,false><<<g1, 256, GEMM_SMEM>>>(pxh, pxl, pw3h + D*D, pw3l + D*D, bk, nullptr, nullptr, pk8h, pk8l, BT, D, D, D, D, D, 8.f);
    // v: transposed hi/lo
    gemm_mma<false,false,false,false,true><<<g1, 256, GEMM_SMEM>>>(pxh, pxl, pw3h + 2*D*D, pw3l + 2*D*D, bv, nullptr, nullptr, pvth, pvtl, BT, D, D, D, D, D, 1.f);

    // attention
    rel_kernel<<<dim3(T, H), 256>>>(relp);
    qk_kernel<<<dim3(4, 4, BATCH*H), 256, GEMM_SMEM>>>();
    softmax_kernel<<<BATCH*H*T/8, 256>>>();
    av_kernel<<<dim3(T/128, BATCH*H), 256, AV_SMEM>>>();

    // src2 = x + att @ proj_w + proj_b
    gemm_mma<true,false,true,false,false><<<g1, 256, GEMM_SMEM>>>(patth, pattl, ppwh, ppwl, proj_b, px, psrc2, nullptr, nullptr, BT, D, D, D, D, D, 1.f);

    // y = rmsnorm(src2)
    rmsnorm_kernel<<<BT, 128>>>(psrc2, norm_w, py, pyh, pyl);

    // h = gelu(y @ ff_w1 + ff_b1)
    dim3 g2(FF / 128, BT / 128);
    gemm_mma<false,true,false,true,false><<<g2, 256, GEMM_SMEM>>>(pyh, pyl, pf1h, pf1l, ff_b1, nullptr, nullptr, phh, phl, BT, FF, D, D, D, FF, 1.f);

    // out = y + h @ ff_w2 + ff_b2
    gemm_mma<true,false,true,false,false><<<g1, 256, GEMM_SMEM>>>(phh, phl, pf2h, pf2l, ff_b2, py, out, nullptr, nullptr, BT, D, FF, FF, FF, D, 1.f);
}

// round 6
// speedup vs baseline: 3.7483x; 1.1570x over previous
#include <cuda_runtime.h>
#include <cuda_fp16.h>
#include <math.h>
#include <stdint.h>

#define BATCH 8
#define T 512
#define D 512
#define H 8
#define HS 64
#define BT (BATCH*T)     // 4096
#define FF 2048

// ===================== device scratch =====================
__device__ __align__(16) float g_x[BT*D];
__device__ __align__(16) float g_q[BT*D];
__device__ __align__(16) float g_src2[BT*D];
__device__ __align__(16) float g_y[BT*D];
__device__ __align__(16) float g_scores[BATCH*H*T*T];   // 64MB fp32
__device__ __align__(16) __half g_rel[BATCH*H*T*T];     // 32MB
__device__ __align__(16) __half g_p[BATCH*H*T*T];       // probs (single fp16)
__device__ __align__(16) __half g_xh[BT*D], g_xl[BT*D];
__device__ __align__(16) __half g_yh[BT*D], g_yl[BT*D];
__device__ __align__(16) __half g_qh[BT*D], g_ql[BT*D];
__device__ __align__(16) __half g_k8h[BT*D], g_k8l[BT*D];
__device__ __align__(16) __half g_vth[BATCH*H*HS*T], g_vtl[BATCH*H*HS*T];
__device__ __align__(16) __half g_att[BT*D];
__device__ __align__(16) __half g_hid[BT*FF];
__device__ __align__(16) __half g_w3h[3*D*D], g_w3l[3*D*D];
__device__ __align__(16) __half g_pwh[D*D],  g_pwl[D*D];
__device__ __align__(16) __half g_f1h[FF*D], g_f1l[FF*D];
__device__ __align__(16) __half g_f2h[D*FF], g_f2l[D*FF];

__device__ __forceinline__ void split2h(float v, __half& h, __half& l) {
    h = __float2half_rn(v);
    l = __float2half_rn(v - __half2float(h));
}

// ===================== primitives =====================
__device__ __forceinline__ void mma_f16(float* d, const uint32_t* a, const uint32_t* b) {
    asm volatile(
        "mma.sync.aligned.m16n8k16.row.col.f32.f16.f16.f32 "
        "{%0,%1,%2,%3}, {%4,%5,%6,%7}, {%8,%9}, {%0,%1,%2,%3};"
        : "+f"(d[0]), "+f"(d[1]), "+f"(d[2]), "+f"(d[3])
        : "r"(a[0]), "r"(a[1]), "r"(a[2]), "r"(a[3]), "r"(b[0]), "r"(b[1]));
}
__device__ __forceinline__ void ldsm4(uint32_t* r, uint32_t addr) {
    asm volatile("ldmatrix.sync.aligned.m8n8.x4.shared.b16 {%0,%1,%2,%3}, [%4];"
        : "=r"(r[0]), "=r"(r[1]), "=r"(r[2]), "=r"(r[3]) : "r"(addr));
}
__device__ __forceinline__ uint32_t smem_to_u32(const void* p) {
    uint32_t a;
    asm("{ .reg .u64 t; cvta.to.shared.u64 t, %1; cvt.u32.u64 %0, t; }" : "=r"(a) : "l"(p));
    return a;
}
__device__ __forceinline__ void cp16(uint32_t s, const void* g) {
    asm volatile("{.reg .u64 gp; cvta.to.global.u64 gp, %1; cp.async.cg.shared.global [%0], [gp], 16;}"
        :: "r"(s), "l"(g) : "memory");
}
#define CP_COMMIT asm volatile("cp.async.commit_group;" ::: "memory")
#define CP_WAIT1  asm volatile("cp.async.wait_group 1;" ::: "memory")
#define CP_WAIT0  asm volatile("cp.async.wait_group 0;" ::: "memory")

// ===================== weight prep (coalesced transpose) =====================
// W[K,N] fp32 -> Wh/Wl [N,K] fp16
__global__ __launch_bounds__(256) void wsplit_t(const float* __restrict__ W,
                                                __half* __restrict__ Wh, __half* __restrict__ Wl,
                                                int K, int N)
{
    __shared__ float tile[32][33];
    const int n0 = blockIdx.x * 32, k0 = blockIdx.y * 32;
    const int tx = threadIdx.x & 31, ty = threadIdx.x >> 5;
    #pragma unroll
    for (int i = 0; i < 32; i += 8)
        tile[ty + i][tx] = W[(size_t)(k0 + ty + i) * N + n0 + tx];
    __syncthreads();
    #pragma unroll
    for (int i = 0; i < 32; i += 8) {
        float v = tile[tx][ty + i];
        __half h, l; split2h(v, h, l);
        size_t o = (size_t)(n0 + ty + i) * K + k0 + tx;
        Wh[o] = h; Wl[o] = l;
    }
}

// qkv: W[h][d][c] -> [mat][n=h*64+c][k=d]
__global__ __launch_bounds__(256) void wsplit_qkv_t(const float* __restrict__ Wq,
                                                    const float* __restrict__ Wk,
                                                    const float* __restrict__ Wv)
{
    __shared__ float tile[32][33];
    const int mat = blockIdx.z >> 3, h = blockIdx.z & 7;
    const int c0 = blockIdx.y * 32, d0 = blockIdx.x * 32;
    const int tx = threadIdx.x & 31, ty = threadIdx.x >> 5;
    const float* W = (mat == 0) ? Wq : (mat == 1) ? Wk : Wv;
    #pragma unroll
    for (int i = 0; i < 32; i += 8)
        tile[ty + i][tx] = W[((size_t)h * D + d0 + ty + i) * HS + c0 + tx];
    __syncthreads();
    #pragma unroll
    for (int i = 0; i < 32; i += 8) {
        float v = tile[tx][ty + i];
        __half hh, ll; split2h(v, hh, ll);
        size_t o = (size_t)mat * D * D + (size_t)(h * HS + c0 + ty + i) * D + d0 + tx;
        g_w3h[o] = hh; g_w3l[o] = ll;
    }
}

// ===================== rmsnorm =====================
__global__ __launch_bounds__(128) void rmsnorm_kernel(
    const float* __restrict__ in, const float* __restrict__ w,
    float* __restrict__ out, __half* __restrict__ outh, __half* __restrict__ outl)
{
    int row = blockIdx.x;
    int tid = threadIdx.x;
    const float4 v = ((const float4*)(in + (size_t)row * D))[tid];
    float ss = v.x*v.x + v.y*v.y + v.z*v.z + v.w*v.w;
    #pragma unroll
    for (int o = 16; o > 0; o >>= 1) ss += __shfl_xor_sync(0xffffffffu, ss, o);
    __shared__ float ws[4];
    if ((tid & 31) == 0) ws[tid >> 5] = ss;
    __syncthreads();
    float total = ws[0] + ws[1] + ws[2] + ws[3];
    float r = rsqrtf(total * (1.0f / (float)D) + 1e-6f);
    const float4 wv = ((const float4*)w)[tid];
    float4 o;
    o.x = v.x * r * wv.x; o.y = v.y * r * wv.y;
    o.z = v.z * r * wv.z; o.w = v.w * r * wv.w;
    ((float4*)(out + (size_t)row * D))[tid] = o;
    __half h0,l0,h1,l1,h2,l2,h3,l3;
    split2h(o.x,h0,l0); split2h(o.y,h1,l1); split2h(o.z,h2,l2); split2h(o.w,h3,l3);
    __half2 hA = __halves2half2(h0,h1), hB = __halves2half2(h2,h3);
    __half2 lA = __halves2half2(l0,l1), lB = __halves2half2(l2,l3);
    size_t base = (size_t)row * D + tid * 4;
    *(__half2*)(outh + base)     = hA;
    *(__half2*)(outh + base + 2) = hB;
    *(__half2*)(outl + base)     = lA;
    *(__half2*)(outl + base + 2) = lB;
}

// ===================== tile constants =====================
static constexpr int TROW  = 80;
static constexpr int TILEB = 128 * TROW;      // 10240
static constexpr int G2_STG  = 3 * TILEB;     // 30720 (A, Bh, Bl)
static constexpr int G2_SMEM = 3 * G2_STG;    // 92160
static constexpr int G3_STG  = 4 * TILEB;     // 40960 (Ah, Al, Bh, Bl)
static constexpr int G3_SMEM = 3 * G3_STG;    // 122880
static constexpr int QK_SMEM = 2 * G3_STG;    // 81920
static constexpr int AV_PB   = 128 * TROW;    // 10240
static constexpr int AV_VB   = 64 * TROW;     // 5120
static constexpr int AV_STG  = AV_PB + 2 * AV_VB;  // 20480
static constexpr int AV_SMEM = 3 * AV_STG;         // 61440

// ===================== gemm3: 3-product (A hi/lo, B hi/lo) =================
// used for q,k: M=BT, N=D, K=D. A ld = K, B ld = K.
template<bool OUTF, bool OUTS2>
__global__ __launch_bounds__(256, 1) void gemm3(
    const __half* __restrict__ Ah, const __half* __restrict__ Al,
    const __half* __restrict__ Bh, const __half* __restrict__ Bl,
    const float* __restrict__ bias,
    float* __restrict__ C, __half* __restrict__ Ch, __half* __restrict__ Cl,
    int M, int N, int K, float osc)
{
    extern __shared__ char sm[];
    const int tid  = threadIdx.x;
    const int wid  = tid >> 5, lane = tid & 31;
    const int warpM = wid & 1, warpN = wid >> 1;
    const int bm = blockIdx.y * 128, bn = blockIdx.x * 128;
    const uint32_t smb = smem_to_u32(sm);

    const int lrow   = tid >> 2;
    const int lchunk = tid & 3;
    const int soff   = lrow * TROW + lchunk * 16;
    const int a_off = (warpM * 64 + (lane & 15)) * TROW + (lane >> 4) * 16;
    const int b_off = (warpN * 32 + ((lane >> 4) << 3) + (lane & 7)) * TROW + ((lane >> 3) & 1) * 16;

    float acc[4][4][4];
    #pragma unroll
    for (int i = 0; i < 4; i++)
        #pragma unroll
        for (int j = 0; j < 4; j++)
            #pragma unroll
            for (int r = 0; r < 4; r++) acc[i][j][r] = 0.f;

    const int nch = K >> 5;
    auto issue = [&](int c, int s) {
        const int k0 = c << 5;
        const uint32_t st = smb + s * G3_STG;
        const __half* pa  = Ah + (size_t)(bm + lrow) * K + k0 + lchunk * 8;
        const __half* pal = Al + (size_t)(bm + lrow) * K + k0 + lchunk * 8;
        const __half* pb  = Bh + (size_t)(bn + lrow) * K + k0 + lchunk * 8;
        const __half* pbl = Bl + (size_t)(bn + lrow) * K + k0 + lchunk * 8;
        cp16(st + soff, pa);                         cp16(st + soff + 64*TROW, pa + (size_t)64*K);
        cp16(st + TILEB + soff, pal);                cp16(st + TILEB + soff + 64*TROW, pal + (size_t)64*K);
        cp16(st + 2*TILEB + soff, pb);               cp16(st + 2*TILEB + soff + 64*TROW, pb + (size_t)64*K);
        cp16(st + 3*TILEB + soff, pbl);              cp16(st + 3*TILEB + soff + 64*TROW, pbl + (size_t)64*K);
        CP_COMMIT;
    };
    issue(0, 0);
    if (nch > 1) issue(1, 1);

    for (int c = 0; c < nch; ++c) {
        if (c + 1 < nch) { CP_WAIT1; } else { CP_WAIT0; }
        __syncthreads();
        if (c + 2 < nch) issue(c + 2, (c + 2) % 3);
        const uint32_t sb = smb + (c % 3) * G3_STG;
        #pragma unroll
        for (int ks = 0; ks < 2; ++ks) {
            uint32_t ahr[4][4], alr[4][4], bhr[2][4], blr[2][4];
            #pragma unroll
            for (int i = 0; i < 4; ++i) {
                ldsm4(ahr[i], sb + a_off + i * (16 * TROW) + ks * 32);
                ldsm4(alr[i], sb + TILEB + a_off + i * (16 * TROW) + ks * 32);
            }
            #pragma unroll
            for (int j = 0; j < 2; ++j) {
                ldsm4(bhr[j], sb + 2*TILEB + b_off + j * (16 * TROW) + ks * 32);
                ldsm4(blr[j], sb + 3*TILEB + b_off + j * (16 * TROW) + ks * 32);
            }
            #pragma unroll
            for (int i = 0; i < 4; ++i)
                #pragma unroll
                for (int j = 0; j < 4; ++j) {
                    uint32_t bfh[2] = { bhr[j >> 1][(j & 1) * 2], bhr[j >> 1][(j & 1) * 2 + 1] };
                    uint32_t bfl[2] = { blr[j >> 1][(j & 1) * 2], blr[j >> 1][(j & 1) * 2 + 1] };
                    mma_f16(acc[i][j], ahr[i], bfh);
                    mma_f16(acc[i][j], ahr[i], bfl);
                    mma_f16(acc[i][j], alr[i], bfh);
                }
        }
    }

    #pragma unroll
    for (int i = 0; i < 4; ++i) {
        const int m0 = bm + warpM * 64 + i * 16 + (lane >> 2);
        #pragma unroll
        for (int j = 0; j < 4; ++j) {
            const int n = bn + warpN * 32 + j * 8 + (lane & 3) * 2;
            const float b0 = bias[n], b1 = bias[n + 1];
            #pragma unroll
            for (int rr = 0; rr < 2; ++rr) {
                const int m = m0 + rr * 8;
                float v0 = (acc[i][j][rr*2+0] + b0) * osc;
                float v1 = (acc[i][j][rr*2+1] + b1) * osc;
                if (OUTF) {
                    float2 o; o.x = v0; o.y = v1;
                    *(float2*)(C + (size_t)m * N + n) = o;
                }
                if (OUTS2) {
                    __half h0,l0,h1,l1;
                    split2h(v0,h0,l0); split2h(v1,h1,l1);
                    *(__half2*)(Ch + (size_t)m * N + n) = __halves2half2(h0,h1);
                    *(__half2*)(Cl + (size_t)m * N + n) = __halves2half2(l0,l1);
                }
            }
        }
    }
}

// ===================== gemm2: 2-product (A single, B hi/lo) ================
template<bool RESID, bool GELU, bool OUTF, bool OUTS1, bool OUTT>
__global__ __launch_bounds__(256, 2) void gemm2(
    const __half* __restrict__ A,
    const __half* __restrict__ Bh, const __half* __restrict__ Bl,
    const float* __restrict__ bias, const float* __restrict__ R,
    float* __restrict__ C, __half* __restrict__ Ch, __half* __restrict__ Cl,
    int M, int N, int K, float osc)
{
    extern __shared__ char sm[];
    const int tid  = threadIdx.x;
    const int wid  = tid >> 5, lane = tid & 31;
    const int warpM = wid & 1, warpN = wid >> 1;
    const int bm = blockIdx.y * 128, bn = blockIdx.x * 128;
    const uint32_t smb = smem_to_u32(sm);

    const int lrow   = tid >> 2;
    const int lchunk = tid & 3;
    const int soff   = lrow * TROW + lchunk * 16;
    const int a_off = (warpM * 64 + (lane & 15)) * TROW + (lane >> 4) * 16;
    const int b_off = (warpN * 32 + ((lane >> 4) << 3) + (lane & 7)) * TROW + ((lane >> 3) & 1) * 16;

    float acc[4][4][4];
    #pragma unroll
    for (int i = 0; i < 4; i++)
        #pragma unroll
        for (int j = 0; j < 4; j++)
            #pragma unroll
            for (int r = 0; r < 4; r++) acc[i][j][r] = 0.f;

    const int nch = K >> 5;
    auto issue = [&](int c, int s) {
        const int k0 = c << 5;
        const uint32_t st = smb + s * G2_STG;
        const __half* pa  = A  + (size_t)(bm + lrow) * K + k0 + lchunk * 8;
        const __half* pb  = Bh + (size_t)(bn + lrow) * K + k0 + lchunk * 8;
        const __half* pbl = Bl + (size_t)(bn + lrow) * K + k0 + lchunk * 8;
        cp16(st + soff, pa);            cp16(st + soff + 64*TROW, pa + (size_t)64*K);
        cp16(st + TILEB + soff, pb);    cp16(st + TILEB + soff + 64*TROW, pb + (size_t)64*K);
        cp16(st + 2*TILEB + soff, pbl); cp16(st + 2*TILEB + soff + 64*TROW, pbl + (size_t)64*K);
        CP_COMMIT;
    };
    issue(0, 0);
    if (nch > 1) issue(1, 1);

    for (int c = 0; c < nch; ++c) {
        if (c + 1 < nch) { CP_WAIT1; } else { CP_WAIT0; }
        __syncthreads();
        if (c + 2 < nch) issue(c + 2, (c + 2) % 3);
        const uint32_t sb = smb + (c % 3) * G2_STG;
        #pragma unroll
        for (int ks = 0; ks < 2; ++ks) {
            uint32_t ar[4][4], bhr[2][4], blr[2][4];
            #pragma unroll
            for (int i = 0; i < 4; ++i)
                ldsm4(ar[i], sb + a_off + i * (16 * TROW) + ks * 32);
            #pragma unroll
            for (int j = 0; j < 2; ++j) {
                ldsm4(bhr[j], sb + TILEB + b_off + j * (16 * TROW) + ks * 32);
                ldsm4(blr[j], sb + 2*TILEB + b_off + j * (16 * TROW) + ks * 32);
            }
            #pragma unroll
            for (int i = 0; i < 4; ++i)
                #pragma unroll
                for (int j = 0; j < 4; ++j) {
                    uint32_t bfh[2] = { bhr[j >> 1][(j & 1) * 2], bhr[j >> 1][(j & 1) * 2 + 1] };
                    uint32_t bfl[2] = { blr[j >> 1][(j & 1) * 2], blr[j >> 1][(j & 1) * 2 + 1] };
                    mma_f16(acc[i][j], ar[i], bfh);
                    mma_f16(acc[i][j], ar[i], bfl);
                }
        }
    }

    #pragma unroll
    for (int i = 0; i < 4; ++i) {
        const int m0 = bm + warpM * 64 + i * 16 + (lane >> 2);
        #pragma unroll
        for (int j = 0; j < 4; ++j) {
            const int n = bn + warpN * 32 + j * 8 + (lane & 3) * 2;
            const float b0 = bias[n], b1 = bias[n + 1];
            #pragma unroll
            for (int rr = 0; rr < 2; ++rr) {
                const int m = m0 + rr * 8;
                float v0 = acc[i][j][rr*2+0] + b0;
                float v1 = acc[i][j][rr*2+1] + b1;
                if (RESID) {
                    const float2 rv = *(const float2*)(R + (size_t)m * N + n);
                    v0 += rv.x; v1 += rv.y;
                }
                v0 *= osc; v1 *= osc;
                if (GELU) {
                    v0 = 0.5f * v0 * (1.f + erff(v0 * 0.70710678118654752f));
                    v1 = 0.5f * v1 * (1.f + erff(v1 * 0.70710678118654752f));
                }
                if (OUTF) {
                    float2 o; o.x = v0; o.y = v1;
                    *(float2*)(C + (size_t)m * N + n) = o;
                }
                if (OUTS1) {
                    *(__half2*)(Ch + (size_t)m * N + n) =
                        __halves2half2(__float2half_rn(v0), __float2half_rn(v1));
                }
                if (OUTT) {
                    const int bb = m >> 9, tt = m & (T - 1);
                    const int hh = n >> 6, cc = n & (HS - 1);
                    __half h0,l0,h1,l1;
                    split2h(v0,h0,l0); split2h(v1,h1,l1);
                    size_t o0 = (((size_t)bb * H + hh) * HS + cc) * T + tt;
                    Ch[o0] = h0; Cl[o0] = l0;
                    Ch[o0 + T] = h1; Cl[o0 + T] = l1;
                }
            }
        }
    }
}

// ===================== rel kernel: R = q . rel (fp32 math, fp16 out) ========
__global__ __launch_bounds__(256) void rel_kernel(const float* __restrict__ relp)
{
    const int t = blockIdx.x;
    const int h = blockIdx.y;
    const int tid = threadIdx.x;

    __shared__ float4 qs4[8 * 16];
    if (tid < 128) {
        int b = tid >> 4, c4 = tid & 15;
        qs4[tid] = *(const float4*)(g_q + ((size_t)(b * T + t)) * D + h * HS + c4 * 4);
    }
    __syncthreads();

    #pragma unroll
    for (int i = 0; i < 2; i++) {
        const int v = tid + i * 256;
        const float4* rel4 = (const float4*)(relp + (((size_t)h * T + t) * T + v) * HS);
        float acc[8];
        #pragma unroll
        for (int b = 0; b < 8; b++) acc[b] = 0.f;
        #pragma unroll 2
        for (int c4 = 0; c4 < 16; c4++) {
            float4 r = rel4[c4];
            #pragma unroll
            for (int b = 0; b < 8; b++) {
                float4 q = qs4[b * 16 + c4];
                acc[b] = fmaf(q.x, r.x, acc[b]);
                acc[b] = fmaf(q.y, r.y, acc[b]);
                acc[b] = fmaf(q.z, r.z, acc[b]);
                acc[b] = fmaf(q.w, r.w, acc[b]);
            }
        }
        #pragma unroll
        for (int b = 0; b < 8; b++)
            g_rel[(((size_t)(b * H + h)) * T + t) * T + v] = __float2half_rn(acc[b]);
    }
}

// ===================== qk kernel: scores = q @ (8k)^T + rel (3-product) ====
__global__ __launch_bounds__(256, 1) void qk_kernel()
{
    extern __shared__ char sm[];
    const int tid  = threadIdx.x;
    const int wid  = tid >> 5, lane = tid & 31;
    const int warpM = wid & 1, warpN = wid >> 1;
    const int bh = blockIdx.z;
    const int b = bh >> 3, h = bh & 7;
    const int bm = blockIdx.y * 128, bn = blockIdx.x * 128;
    const uint32_t smb = smem_to_u32(sm);

    const __half* Ah = g_qh  + (size_t)(b * T) * D + h * HS;
    const __half* Al = g_ql  + (size_t)(b * T) * D + h * HS;
    const __half* Bh = g_k8h + (size_t)(b * T) * D + h * HS;
    const __half* Bl = g_k8l + (size_t)(b * T) * D + h * HS;

    const int lrow   = tid >> 2;
    const int lchunk = tid & 3;
    const int soff   = lrow * TROW + lchunk * 16;
    const int a_off = (warpM * 64 + (lane & 15)) * TROW + (lane >> 4) * 16;
    const int b_off = (warpN * 32 + ((lane >> 4) << 3) + (lane & 7)) * TROW + ((lane >> 3) & 1) * 16;

    float acc[4][4][4];
    #pragma unroll
    for (int i = 0; i < 4; i++)
        #pragma unroll
        for (int j = 0; j < 4; j++)
            #pragma unroll
            for (int r = 0; r < 4; r++) acc[i][j][r] = 0.f;

    #pragma unroll
    for (int c = 0; c < 2; ++c) {
        const uint32_t st = smb + c * G3_STG;
        const int k0 = c << 5;
        cp16(st + soff,                        Ah + (size_t)(bm + lrow) * D + k0 + lchunk * 8);
        cp16(st + soff + 64*TROW,              Ah + (size_t)(bm + lrow + 64) * D + k0 + lchunk * 8);
        cp16(st + TILEB + soff,                Al + (size_t)(bm + lrow) * D + k0 + lchunk * 8);
        cp16(st + TILEB + soff + 64*TROW,      Al + (size_t)(bm + lrow + 64) * D + k0 + lchunk * 8);
        cp16(st + 2*TILEB + soff,              Bh + (size_t)(bn + lrow) * D + k0 + lchunk * 8);
        cp16(st + 2*TILEB + soff + 64*TROW,    Bh + (size_t)(bn + lrow + 64) * D + k0 + lchunk * 8);
        cp16(st + 3*TILEB + soff,              Bl + (size_t)(bn + lrow) * D + k0 + lchunk * 8);
        cp16(st + 3*TILEB + soff + 64*TROW,    Bl + (size_t)(bn + lrow + 64) * D + k0 + lchunk * 8);
    }
    CP_COMMIT;
    CP_WAIT0;
    __syncthreads();

    #pragma unroll
    for (int c = 0; c < 2; ++c) {
        const uint32_t sb = smb + c * G3_STG;
        #pragma unroll
        for (int ks = 0; ks < 2; ++ks) {
            uint32_t ahr[4][4], alr[4][4], bhr[2][4], blr[2][4];
            #pragma unroll
            for (int i = 0; i < 4; ++i) {
                ldsm4(ahr[i], sb + a_off + i * (16 * TROW) + ks * 32);
                ldsm4(alr[i], sb + TILEB + a_off + i * (16 * TROW) + ks * 32);
            }
            #pragma unroll
            for (int j = 0; j < 2; ++j) {
                ldsm4(bhr[j], sb + 2*TILEB + b_off + j * (16 * TROW) + ks * 32);
                ldsm4(blr[j], sb + 3*TILEB + b_off + j * (16 * TROW) + ks * 32);
            }
            #pragma unroll
            for (int i = 0; i < 4; ++i)
                #pragma unroll
                for (int j = 0; j < 4; ++j) {
                    uint32_t bfh[2] = { bhr[j >> 1][(j & 1) * 2], bhr[j >> 1][(j & 1) * 2 + 1] };
                    uint32_t bfl[2] = { blr[j >> 1][(j & 1) * 2], blr[j >> 1][(j & 1) * 2 + 1] };
                    mma_f16(acc[i][j], ahr[i], bfh);
                    mma_f16(acc[i][j], ahr[i], bfl);
                    mma_f16(acc[i][j], alr[i], bfh);
                }
        }
    }

    float* Cb = g_scores + (size_t)bh * T * T;
    const __half* Rb = g_rel + (size_t)bh * T * T;
    #pragma unroll
    for (int i = 0; i < 4; ++i) {
        const int m0 = bm + warpM * 64 + i * 16 + (lane >> 2);
        #pragma unroll
        for (int j = 0; j < 4; ++j) {
            const int n = bn + warpN * 32 + j * 8 + (lane & 3) * 2;
            #pragma unroll
            for (int rr = 0; rr < 2; ++rr) {
                const int m = m0 + rr * 8;
                __half2 rv = *(const __half2*)(Rb + (size_t)m * T + n);
                float2 o;
                o.x = acc[i][j][rr*2+0] + __half2float(rv.x);
                o.y = acc[i][j][rr*2+1] + __half2float(rv.y);
                *(float2*)(Cb + (size_t)m * T + n) = o;
            }
        }
    }
}

// ===================== softmax: warp per row -> probs fp16 =================
__global__ __launch_bounds__(256) void softmax_kernel()
{
    const int r = blockIdx.x * 8 + (threadIdx.x >> 5);
    const int lane = threadIdx.x & 31;
    const float* row = g_scores + (size_t)r * T;

    float4 v[4];
    float m = -1e30f;
    #pragma unroll
    for (int j = 0; j < 4; ++j) {
        v[j] = ((const float4*)row)[lane + 32 * j];
        m = fmaxf(m, fmaxf(fmaxf(v[j].x, v[j].y), fmaxf(v[j].z, v[j].w)));
    }
    #pragma unroll
    for (int o = 16; o > 0; o >>= 1) m = fmaxf(m, __shfl_xor_sync(0xffffffffu, m, o));
    float s = 0.f;
    #pragma unroll
    for (int j = 0; j < 4; ++j) {
        v[j].x = __expf(v[j].x - m); v[j].y = __expf(v[j].y - m);
        v[j].z = __expf(v[j].z - m); v[j].w = __expf(v[j].w - m);
        s += v[j].x + v[j].y + v[j].z + v[j].w;
    }
    #pragma unroll
    for (int o = 16; o > 0; o >>= 1) s += __shfl_xor_sync(0xffffffffu, s, o);
    const float inv = 1.f / s;
    #pragma unroll
    for (int j = 0; j < 4; ++j) {
        size_t base = (size_t)r * T + (lane + 32 * j) * 4;
        *(__half2*)(g_p + base) =
            __halves2half2(__float2half_rn(v[j].x * inv), __float2half_rn(v[j].y * inv));
        *(__half2*)(g_p + base + 2) =
            __halves2half2(__float2half_rn(v[j].z * inv), __float2half_rn(v[j].w * inv));
    }
}

// ===================== AV kernel: out = P @ V (2-product) ===================
__global__ __launch_bounds__(256, 2) void av_kernel()
{
    extern __shared__ char sm[];
    const int tid  = threadIdx.x;
    const int wid  = tid >> 5, lane = tid & 31;
    const int warpM = wid & 3, warpN = wid >> 2;
    const int bh = blockIdx.y;
    const int b = bh >> 3, h = bh & 7;
    const int t0 = blockIdx.x * 128;
    const uint32_t smb = smem_to_u32(sm);

    const __half* P  = g_p   + ((size_t)bh * T + t0) * T;
    const __half* Vh = g_vth + (size_t)bh * HS * T;
    const __half* Vl = g_vtl + (size_t)bh * HS * T;

    const int lrow   = tid >> 2;
    const int lchunk = tid & 3;
    const int soff   = lrow * TROW + lchunk * 16;
    const int a_off = (warpM * 32 + (lane & 15)) * TROW + (lane >> 4) * 16;
    const int b_off = (warpN * 32 + ((lane >> 4) << 3) + (lane & 7)) * TROW + ((lane >> 3) & 1) * 16;

    float acc[2][4][4];
    #pragma unroll
    for (int i = 0; i < 2; i++)
        #pragma unroll
        for (int j = 0; j < 4; j++)
            #pragma unroll
            for (int r = 0; r < 4; r++) acc[i][j][r] = 0.f;

    const int nch = T >> 5;  // 16
    auto issue = [&](int c, int s) {
        const int k0 = c << 5;
        const uint32_t st = smb + s * AV_STG;
        cp16(st + soff,                 P  + (size_t)lrow * T + k0 + lchunk * 8);
        cp16(st + soff + 64*TROW,       P  + (size_t)(lrow + 64) * T + k0 + lchunk * 8);
        cp16(st + AV_PB + soff,         Vh + (size_t)lrow * T + k0 + lchunk * 8);
        cp16(st + AV_PB + AV_VB + soff, Vl + (size_t)lrow * T + k0 + lchunk * 8);
        CP_COMMIT;
    };
    issue(0, 0);
    issue(1, 1);

    for (int c = 0; c < nch; ++c) {
        if (c + 1 < nch) { CP_WAIT1; } else { CP_WAIT0; }
        __syncthreads();
        if (c + 2 < nch) issue(c + 2, (c + 2) % 3);
        const uint32_t sb = smb + (c % 3) * AV_STG;
        #pragma unroll
        for (int ks = 0; ks < 2; ++ks) {
            uint32_t ar[2][4], bhr[2][4], blr[2][4];
            #pragma unroll
            for (int i = 0; i < 2; ++i)
                ldsm4(ar[i], sb + a_off + i * (16 * TROW) + ks * 32);
            #pragma unroll
            for (int j = 0; j < 2; ++j) {
                ldsm4(bhr[j], sb + AV_PB + b_off + j * (16 * TROW) + ks * 32);
                ldsm4(blr[j], sb + AV_PB + AV_VB + b_off + j * (16 * TROW) + ks * 32);
            }
            #pragma unroll
            for (int i = 0; i < 2; ++i)
                #pragma unroll
                for (int j = 0; j < 4; ++j) {
                    uint32_t bfh[2] = { bhr[j >> 1][(j & 1) * 2], bhr[j >> 1][(j & 1) * 2 + 1] };
                    uint32_t bfl[2] = { blr[j >> 1][(j & 1) * 2], blr[j >> 1][(j & 1) * 2 + 1] };
                    mma_f16(acc[i][j], ar[i], bfh);
                    mma_f16(acc[i][j], ar[i], bfl);
                }
        }
    }

    #pragma unroll
    for (int i = 0; i < 2; ++i) {
        #pragma unroll
        for (int j = 0; j < 4; ++j) {
            const int cc = warpN * 32 + j * 8 + (lane & 3) * 2;
            #pragma unroll
            for (int rr = 0; rr < 2; ++rr) {
                const int m = t0 + warpM * 32 + i * 16 + (lane >> 2) + rr * 8;
                size_t off = ((size_t)(b * T + m)) * D + h * HS + cc;
                *(__half2*)(g_att + off) =
                    __halves2half2(__float2half_rn(acc[i][j][rr*2+0]),
                                   __float2half_rn(acc[i][j][rr*2+1]));
            }
        }
    }
}

// ===================== launch ==============================================
extern "C" void kernel_launch(void* const* d_in, const int* in_sizes, int n_in,
                              void* d_out, int out_size)
{
    (void)in_sizes; (void)n_in; (void)out_size;
    const float* src    = (const float*)d_in[0];
    const float* norm_w = (const float*)d_in[1];
    const float* Wq     = (const float*)d_in[2];
    const float* bq     = (const float*)d_in[3];
    const float* Wk     = (const float*)d_in[4];
    const float* bk     = (const float*)d_in[5];
    const float* Wv     = (const float*)d_in[6];
    const float* bv     = (const float*)d_in[7];
    const float* relp   = (const float*)d_in[8];
    const float* proj_w = (const float*)d_in[9];
    const float* proj_b = (const float*)d_in[10];
    const float* ff_w1  = (const float*)d_in[11];
    const float* ff_b1  = (const float*)d_in[12];
    const float* ff_w2  = (const float*)d_in[13];
    const float* ff_b2  = (const float*)d_in[14];
    float* out = (float*)d_out;

    float *px, *pq, *psrc2, *py;
    __half *pxh, *pxl, *pyh, *pyl, *pqh, *pql, *pk8h, *pk8l, *pvth, *pvtl;
    __half *patt, *phid;
    __half *pw3h, *pw3l, *ppwh, *ppwl, *pf1h, *pf1l, *pf2h, *pf2l;
    cudaGetSymbolAddress((void**)&px,    g_x);
    cudaGetSymbolAddress((void**)&pq,    g_q);
    cudaGetSymbolAddress((void**)&psrc2, g_src2);
    cudaGetSymbolAddress((void**)&py,    g_y);
    cudaGetSymbolAddress((void**)&pxh,   g_xh);
    cudaGetSymbolAddress((void**)&pxl,   g_xl);
    cudaGetSymbolAddress((void**)&pyh,   g_yh);
    cudaGetSymbolAddress((void**)&pyl,   g_yl);
    cudaGetSymbolAddress((void**)&pqh,   g_qh);
    cudaGetSymbolAddress((void**)&pql,   g_ql);
    cudaGetSymbolAddress((void**)&pk8h,  g_k8h);
    cudaGetSymbolAddress((void**)&pk8l,  g_k8l);
    cudaGetSymbolAddress((void**)&pvth,  g_vth);
    cudaGetSymbolAddress((void**)&pvtl,  g_vtl);
    cudaGetSymbolAddress((void**)&patt,  g_att);
    cudaGetSymbolAddress((void**)&phid,  g_hid);
    cudaGetSymbolAddress((void**)&pw3h,  g_w3h);
    cudaGetSymbolAddress((void**)&pw3l,  g_w3l);
    cudaGetSymbolAddress((void**)&ppwh,  g_pwh);
    cudaGetSymbolAddress((void**)&ppwl,  g_pwl);
    cudaGetSymbolAddress((void**)&pf1h,  g_f1h);
    cudaGetSymbolAddress((void**)&pf1l,  g_f1l);
    cudaGetSymbolAddress((void**)&pf2h,  g_f2h);
    cudaGetSymbolAddress((void**)&pf2l,  g_f2l);

    cudaFuncSetAttribute(gemm3<true, true>,  cudaFuncAttributeMaxDynamicSharedMemorySize, G3_SMEM);
    cudaFuncSetAttribute(gemm3<false,true>,  cudaFuncAttributeMaxDynamicSharedMemorySize, G3_SMEM);
    cudaFuncSetAttribute(gemm2<false,false,false,false,true>,  cudaFuncAttributeMaxDynamicSharedMemorySize, G2_SMEM);
    cudaFuncSetAttribute(gemm2<true, false,true, false,false>, cudaFuncAttributeMaxDynamicSharedMemorySize, G2_SMEM);
    cudaFuncSetAttribute(gemm2<false,true, false,true, false>, cudaFuncAttributeMaxDynamicSharedMemorySize, G2_SMEM);
    cudaFuncSetAttribute(qk_kernel, cudaFuncAttributeMaxDynamicSharedMemorySize, QK_SMEM);
    cudaFuncSetAttribute(av_kernel, cudaFuncAttributeMaxDynamicSharedMemorySize, AV_SMEM);

    // weight prep (coalesced transpose + split)
    wsplit_qkv_t<<<dim3(D/32, HS/32, 24), 256>>>(Wq, Wk, Wv);
    wsplit_t<<<dim3(D/32, D/32),  256>>>(proj_w, ppwh, ppwl, D, D);
    wsplit_t<<<dim3(FF/32, D/32), 256>>>(ff_w1, pf1h, pf1l, D, FF);
    wsplit_t<<<dim3(D/32, FF/32), 256>>>(ff_w2, pf2h, pf2l, FF, D);

    // x = rmsnorm(src)
    rmsnorm_kernel<<<BT, 128>>>(src, norm_w, px, pxh, pxl);

    dim3 g1(D / 128, BT / 128);   // (4, 32)
    // q: fp32 + hi/lo fp16 (3-product)
    gemm3<true, true><<<g1, 256, G3_SMEM>>>(pxh, pxl, pw3h,       pw3l,       bq, pq, pqh, pql, BT, D, D, 1.f);
    // k8: hi/lo fp16 (3-product, scaled by 8)
    gemm3<false,true><<<g1, 256, G3_SMEM>>>(pxh, pxl, pw3h + D*D, pw3l + D*D, bk, nullptr, pk8h, pk8l, BT, D, D, 8.f);
    // v: transposed hi/lo fp16 (2-product)
    gemm2<false,false,false,false,true><<<g1, 256, G2_SMEM>>>(pxh, pw3h + 2*D*D, pw3l + 2*D*D, bv, nullptr, nullptr, pvth, pvtl, BT, D, D, 1.f);

    // attention
    rel_kernel<<<dim3(T, H), 256>>>(relp);
    qk_kernel<<<dim3(4, 4, BATCH*H), 256, QK_SMEM>>>();
    softmax_kernel<<<BATCH*H*T/8, 256>>>();
    av_kernel<<<dim3(T/128, BATCH*H), 256, AV_SMEM>>>();

    // src2 = x + att @ proj_w + proj_b
    gemm2<true,false,true,false,false><<<g1, 256, G2_SMEM>>>(patt, ppwh, ppwl, proj_b, px, psrc2, nullptr, nullptr, BT, D, D, 1.f);

    // y = rmsnorm(src2)
    rmsnorm_kernel<<<BT, 128>>>(psrc2, norm_w, py, pyh, pyl);

    // h = gelu(y @ ff_w1 + ff_b1)
    dim3 g2(FF / 128, BT / 128);  // (16, 32)
    gemm2<false,true,false,true,false><<<g2, 256, G2_SMEM>>>(pyh, pf1h, pf1l, ff_b1, nullptr, nullptr, phid, nullptr, BT, FF, D, 1.f);

    // out = y + h @ ff_w2 + ff_b2
    gemm2<true,false,true,false,false><<<g1, 256, G2_SMEM>>>(phid, pf2h, pf2l, ff_b2, py, out, nullptr, nullptr, BT, D, FF, 1.f);
}

// round 7
// speedup vs baseline: 3.7684x; 1.0054x over previous
#include <cuda_runtime.h>
#include <cuda_fp16.h>
#include <math.h>
#include <stdint.h>

#define BATCH 8
#define T 512
#define D 512
#define H 8
#define HS 64
#define BT (BATCH*T)     // 4096
#define FF 2048

// ===================== device scratch =====================
__device__ __align__(16) float g_x[BT*D];
__device__ __align__(16) float g_q[BT*D];
__device__ __align__(16) float g_src2[BT*D];
__device__ __align__(16) float g_y[BT*D];
__device__ __align__(16) __half g_rel[BATCH*H*T*T];     // 32MB
__device__ __align__(16) __half g_xh[BT*D], g_xl[BT*D];
__device__ __align__(16) __half g_yh[BT*D], g_yl[BT*D];
__device__ __align__(16) __half g_qh[BT*D], g_ql[BT*D];
__device__ __align__(16) __half g_k8h[BT*D], g_k8l[BT*D];
__device__ __align__(16) __half g_vth[BATCH*H*HS*T], g_vtl[BATCH*H*HS*T];
__device__ __align__(16) __half g_att[BT*D];
__device__ __align__(16) __half g_hid[BT*FF];
__device__ __align__(16) __half g_w3h[3*D*D], g_w3l[3*D*D];
__device__ __align__(16) __half g_pwh[D*D],  g_pwl[D*D];
__device__ __align__(16) __half g_f1h[FF*D], g_f1l[FF*D];
__device__ __align__(16) __half g_f2h[D*FF], g_f2l[D*FF];

__device__ __forceinline__ void split2h(float v, __half& h, __half& l) {
    h = __float2half_rn(v);
    l = __float2half_rn(v - __half2float(h));
}

// ===================== primitives =====================
__device__ __forceinline__ void mma_f16(float* d, const uint32_t* a, const uint32_t* b) {
    asm volatile(
        "mma.sync.aligned.m16n8k16.row.col.f32.f16.f16.f32 "
        "{%0,%1,%2,%3}, {%4,%5,%6,%7}, {%8,%9}, {%0,%1,%2,%3};"
        : "+f"(d[0]), "+f"(d[1]), "+f"(d[2]), "+f"(d[3])
        : "r"(a[0]), "r"(a[1]), "r"(a[2]), "r"(a[3]), "r"(b[0]), "r"(b[1]));
}
__device__ __forceinline__ void ldsm4(uint32_t* r, uint32_t addr) {
    asm volatile("ldmatrix.sync.aligned.m8n8.x4.shared.b16 {%0,%1,%2,%3}, [%4];"
        : "=r"(r[0]), "=r"(r[1]), "=r"(r[2]), "=r"(r[3]) : "r"(addr));
}
__device__ __forceinline__ uint32_t smem_to_u32(const void* p) {
    uint32_t a;
    asm("{ .reg .u64 t; cvta.to.shared.u64 t, %1; cvt.u32.u64 %0, t; }" : "=r"(a) : "l"(p));
    return a;
}
__device__ __forceinline__ void cp16(uint32_t s, const void* g) {
    asm volatile("{.reg .u64 gp; cvta.to.global.u64 gp, %1; cp.async.cg.shared.global [%0], [gp], 16;}"
        :: "r"(s), "l"(g) : "memory");
}
#define CP_COMMIT asm volatile("cp.async.commit_group;" ::: "memory")
#define CP_WAIT1  asm volatile("cp.async.wait_group 1;" ::: "memory")
#define CP_WAIT0  asm volatile("cp.async.wait_group 0;" ::: "memory")

// ===================== weight prep (coalesced transpose) =====================
__global__ __launch_bounds__(256) void wsplit_t(const float* __restrict__ W,
                                                __half* __restrict__ Wh, __half* __restrict__ Wl,
                                                int K, int N)
{
    __shared__ float tile[32][33];
    const int n0 = blockIdx.x * 32, k0 = blockIdx.y * 32;
    const int tx = threadIdx.x & 31, ty = threadIdx.x >> 5;
    #pragma unroll
    for (int i = 0; i < 32; i += 8)
        tile[ty + i][tx] = W[(size_t)(k0 + ty + i) * N + n0 + tx];
    __syncthreads();
    #pragma unroll
    for (int i = 0; i < 32; i += 8) {
        float v = tile[tx][ty + i];
        __half h, l; split2h(v, h, l);
        size_t o = (size_t)(n0 + ty + i) * K + k0 + tx;
        Wh[o] = h; Wl[o] = l;
    }
}

__global__ __launch_bounds__(256) void wsplit_qkv_t(const float* __restrict__ Wq,
                                                    const float* __restrict__ Wk,
                                                    const float* __restrict__ Wv)
{
    __shared__ float tile[32][33];
    const int mat = blockIdx.z >> 3, h = blockIdx.z & 7;
    const int c0 = blockIdx.y * 32, d0 = blockIdx.x * 32;
    const int tx = threadIdx.x & 31, ty = threadIdx.x >> 5;
    const float* W = (mat == 0) ? Wq : (mat == 1) ? Wk : Wv;
    #pragma unroll
    for (int i = 0; i < 32; i += 8)
        tile[ty + i][tx] = W[((size_t)h * D + d0 + ty + i) * HS + c0 + tx];
    __syncthreads();
    #pragma unroll
    for (int i = 0; i < 32; i += 8) {
        float v = tile[tx][ty + i];
        __half hh, ll; split2h(v, hh, ll);
        size_t o = (size_t)mat * D * D + (size_t)(h * HS + c0 + ty + i) * D + d0 + tx;
        g_w3h[o] = hh; g_w3l[o] = ll;
    }
}

// ===================== rmsnorm =====================
__global__ __launch_bounds__(128) void rmsnorm_kernel(
    const float* __restrict__ in, const float* __restrict__ w,
    float* __restrict__ out, __half* __restrict__ outh, __half* __restrict__ outl)
{
    int row = blockIdx.x;
    int tid = threadIdx.x;
    const float4 v = ((const float4*)(in + (size_t)row * D))[tid];
    float ss = v.x*v.x + v.y*v.y + v.z*v.z + v.w*v.w;
    #pragma unroll
    for (int o = 16; o > 0; o >>= 1) ss += __shfl_xor_sync(0xffffffffu, ss, o);
    __shared__ float ws[4];
    if ((tid & 31) == 0) ws[tid >> 5] = ss;
    __syncthreads();
    float total = ws[0] + ws[1] + ws[2] + ws[3];
    float r = rsqrtf(total * (1.0f / (float)D) + 1e-6f);
    const float4 wv = ((const float4*)w)[tid];
    float4 o;
    o.x = v.x * r * wv.x; o.y = v.y * r * wv.y;
    o.z = v.z * r * wv.z; o.w = v.w * r * wv.w;
    ((float4*)(out + (size_t)row * D))[tid] = o;
    __half h0,l0,h1,l1,h2,l2,h3,l3;
    split2h(o.x,h0,l0); split2h(o.y,h1,l1); split2h(o.z,h2,l2); split2h(o.w,h3,l3);
    size_t base = (size_t)row * D + tid * 4;
    *(__half2*)(outh + base)     = __halves2half2(h0,h1);
    *(__half2*)(outh + base + 2) = __halves2half2(h2,h3);
    *(__half2*)(outl + base)     = __halves2half2(l0,l1);
    *(__half2*)(outl + base + 2) = __halves2half2(l2,l3);
}

// ===================== tile constants =====================
static constexpr int TROW  = 80;
static constexpr int TILEB = 128 * TROW;      // 10240
static constexpr int G2_STG  = 3 * TILEB;     // 30720
static constexpr int G2_SMEM = 3 * G2_STG;    // 92160
static constexpr int G3_STG  = 4 * TILEB;     // 40960
static constexpr int G3_SMEM = 3 * G3_STG;    // 122880

// ===================== merged q/k GEMM (3-product, z selects) ==============
__global__ __launch_bounds__(256, 1) void gemm_qk(
    const float* __restrict__ bq, const float* __restrict__ bk)
{
    extern __shared__ char sm[];
    const int z = blockIdx.z;               // 0: q, 1: k8
    const __half* Ah = g_xh;
    const __half* Al = g_xl;
    const __half* Bh = g_w3h + (size_t)z * D * D;
    const __half* Bl = g_w3l + (size_t)z * D * D;
    const float* bias = z ? bk : bq;
    const float osc = z ? 8.f : 1.f;
    const int K = D, N = D;

    const int tid  = threadIdx.x;
    const int wid  = tid >> 5, lane = tid & 31;
    const int warpM = wid & 1, warpN = wid >> 1;
    const int bm = blockIdx.y * 128, bn = blockIdx.x * 128;
    const uint32_t smb = smem_to_u32(sm);

    const int lrow   = tid >> 2;
    const int lchunk = tid & 3;
    const int soff   = lrow * TROW + lchunk * 16;
    const int a_off = (warpM * 64 + (lane & 15)) * TROW + (lane >> 4) * 16;
    const int b_off = (warpN * 32 + ((lane >> 4) << 3) + (lane & 7)) * TROW + ((lane >> 3) & 1) * 16;

    float acc[4][4][4];
    #pragma unroll
    for (int i = 0; i < 4; i++)
        #pragma unroll
        for (int j = 0; j < 4; j++)
            #pragma unroll
            for (int r = 0; r < 4; r++) acc[i][j][r] = 0.f;

    const int nch = K >> 5;
    auto issue = [&](int c, int s) {
        const int k0 = c << 5;
        const uint32_t st = smb + s * G3_STG;
        const __half* pa  = Ah + (size_t)(bm + lrow) * K + k0 + lchunk * 8;
        const __half* pal = Al + (size_t)(bm + lrow) * K + k0 + lchunk * 8;
        const __half* pb  = Bh + (size_t)(bn + lrow) * K + k0 + lchunk * 8;
        const __half* pbl = Bl + (size_t)(bn + lrow) * K + k0 + lchunk * 8;
        cp16(st + soff, pa);            cp16(st + soff + 64*TROW, pa + (size_t)64*K);
        cp16(st + TILEB + soff, pal);   cp16(st + TILEB + soff + 64*TROW, pal + (size_t)64*K);
        cp16(st + 2*TILEB + soff, pb);  cp16(st + 2*TILEB + soff + 64*TROW, pb + (size_t)64*K);
        cp16(st + 3*TILEB + soff, pbl); cp16(st + 3*TILEB + soff + 64*TROW, pbl + (size_t)64*K);
        CP_COMMIT;
    };
    issue(0, 0);
    issue(1, 1);

    for (int c = 0; c < nch; ++c) {
        if (c + 1 < nch) { CP_WAIT1; } else { CP_WAIT0; }
        __syncthreads();
        if (c + 2 < nch) issue(c + 2, (c + 2) % 3);
        const uint32_t sb = smb + (c % 3) * G3_STG;
        #pragma unroll
        for (int ks = 0; ks < 2; ++ks) {
            uint32_t ahr[4][4], alr[4][4], bhr[2][4], blr[2][4];
            #pragma unroll
            for (int i = 0; i < 4; ++i) {
                ldsm4(ahr[i], sb + a_off + i * (16 * TROW) + ks * 32);
                ldsm4(alr[i], sb + TILEB + a_off + i * (16 * TROW) + ks * 32);
            }
            #pragma unroll
            for (int j = 0; j < 2; ++j) {
                ldsm4(bhr[j], sb + 2*TILEB + b_off + j * (16 * TROW) + ks * 32);
                ldsm4(blr[j], sb + 3*TILEB + b_off + j * (16 * TROW) + ks * 32);
            }
            #pragma unroll
            for (int i = 0; i < 4; ++i)
                #pragma unroll
                for (int j = 0; j < 4; ++j) {
                    uint32_t bfh[2] = { bhr[j >> 1][(j & 1) * 2], bhr[j >> 1][(j & 1) * 2 + 1] };
                    uint32_t bfl[2] = { blr[j >> 1][(j & 1) * 2], blr[j >> 1][(j & 1) * 2 + 1] };
                    mma_f16(acc[i][j], ahr[i], bfh);
                    mma_f16(acc[i][j], ahr[i], bfl);
                    mma_f16(acc[i][j], alr[i], bfh);
                }
        }
    }

    #pragma unroll
    for (int i = 0; i < 4; ++i) {
        const int m0 = bm + warpM * 64 + i * 16 + (lane >> 2);
        #pragma unroll
        for (int j = 0; j < 4; ++j) {
            const int n = bn + warpN * 32 + j * 8 + (lane & 3) * 2;
            const float b0 = bias[n], b1 = bias[n + 1];
            #pragma unroll
            for (int rr = 0; rr < 2; ++rr) {
                const int m = m0 + rr * 8;
                float v0 = (acc[i][j][rr*2+0] + b0) * osc;
                float v1 = (acc[i][j][rr*2+1] + b1) * osc;
                __half h0,l0,h1,l1;
                split2h(v0,h0,l0); split2h(v1,h1,l1);
                if (z == 0) {
                    float2 o; o.x = v0; o.y = v1;
                    *(float2*)(g_q + (size_t)m * N + n) = o;
                    *(__half2*)(g_qh + (size_t)m * N + n) = __halves2half2(h0,h1);
                    *(__half2*)(g_ql + (size_t)m * N + n) = __halves2half2(l0,l1);
                } else {
                    *(__half2*)(g_k8h + (size_t)m * N + n) = __halves2half2(h0,h1);
                    *(__half2*)(g_k8l + (size_t)m * N + n) = __halves2half2(l0,l1);
                }
            }
        }
    }
}

// ===================== gemm2: 2-product (A single, B hi/lo) ================
template<bool RESID, bool GELU, bool OUTF, bool OUTS1, bool OUTT>
__global__ __launch_bounds__(256, 2) void gemm2(
    const __half* __restrict__ A,
    const __half* __restrict__ Bh, const __half* __restrict__ Bl,
    const float* __restrict__ bias, const float* __restrict__ R,
    float* __restrict__ C, __half* __restrict__ Ch, __half* __restrict__ Cl,
    int M, int N, int K, float osc)
{
    extern __shared__ char sm[];
    const int tid  = threadIdx.x;
    const int wid  = tid >> 5, lane = tid & 31;
    const int warpM = wid & 1, warpN = wid >> 1;
    const int bm = blockIdx.y * 128, bn = blockIdx.x * 128;
    const uint32_t smb = smem_to_u32(sm);

    const int lrow   = tid >> 2;
    const int lchunk = tid & 3;
    const int soff   = lrow * TROW + lchunk * 16;
    const int a_off = (warpM * 64 + (lane & 15)) * TROW + (lane >> 4) * 16;
    const int b_off = (warpN * 32 + ((lane >> 4) << 3) + (lane & 7)) * TROW + ((lane >> 3) & 1) * 16;

    float acc[4][4][4];
    #pragma unroll
    for (int i = 0; i < 4; i++)
        #pragma unroll
        for (int j = 0; j < 4; j++)
            #pragma unroll
            for (int r = 0; r < 4; r++) acc[i][j][r] = 0.f;

    const int nch = K >> 5;
    auto issue = [&](int c, int s) {
        const int k0 = c << 5;
        const uint32_t st = smb + s * G2_STG;
        const __half* pa  = A  + (size_t)(bm + lrow) * K + k0 + lchunk * 8;
        const __half* pb  = Bh + (size_t)(bn + lrow) * K + k0 + lchunk * 8;
        const __half* pbl = Bl + (size_t)(bn + lrow) * K + k0 + lchunk * 8;
        cp16(st + soff, pa);            cp16(st + soff + 64*TROW, pa + (size_t)64*K);
        cp16(st + TILEB + soff, pb);    cp16(st + TILEB + soff + 64*TROW, pb + (size_t)64*K);
        cp16(st + 2*TILEB + soff, pbl); cp16(st + 2*TILEB + soff + 64*TROW, pbl + (size_t)64*K);
        CP_COMMIT;
    };
    issue(0, 0);
    if (nch > 1) issue(1, 1);

    for (int c = 0; c < nch; ++c) {
        if (c + 1 < nch) { CP_WAIT1; } else { CP_WAIT0; }
        __syncthreads();
        if (c + 2 < nch) issue(c + 2, (c + 2) % 3);
        const uint32_t sb = smb + (c % 3) * G2_STG;
        #pragma unroll
        for (int ks = 0; ks < 2; ++ks) {
            uint32_t ar[4][4], bhr[2][4], blr[2][4];
            #pragma unroll
            for (int i = 0; i < 4; ++i)
                ldsm4(ar[i], sb + a_off + i * (16 * TROW) + ks * 32);
            #pragma unroll
            for (int j = 0; j < 2; ++j) {
                ldsm4(bhr[j], sb + TILEB + b_off + j * (16 * TROW) + ks * 32);
                ldsm4(blr[j], sb + 2*TILEB + b_off + j * (16 * TROW) + ks * 32);
            }
            #pragma unroll
            for (int i = 0; i < 4; ++i)
                #pragma unroll
                for (int j = 0; j < 4; ++j) {
                    uint32_t bfh[2] = { bhr[j >> 1][(j & 1) * 2], bhr[j >> 1][(j & 1) * 2 + 1] };
                    uint32_t bfl[2] = { blr[j >> 1][(j & 1) * 2], blr[j >> 1][(j & 1) * 2 + 1] };
                    mma_f16(acc[i][j], ar[i], bfh);
                    mma_f16(acc[i][j], ar[i], bfl);
                }
        }
    }

    #pragma unroll
    for (int i = 0; i < 4; ++i) {
        const int m0 = bm + warpM * 64 + i * 16 + (lane >> 2);
        #pragma unroll
        for (int j = 0; j < 4; ++j) {
            const int n = bn + warpN * 32 + j * 8 + (lane & 3) * 2;
            const float b0 = bias[n], b1 = bias[n + 1];
            #pragma unroll
            for (int rr = 0; rr < 2; ++rr) {
                const int m = m0 + rr * 8;
                float v0 = acc[i][j][rr*2+0] + b0;
                float v1 = acc[i][j][rr*2+1] + b1;
                if (RESID) {
                    const float2 rv = *(const float2*)(R + (size_t)m * N + n);
                    v0 += rv.x; v1 += rv.y;
                }
                v0 *= osc; v1 *= osc;
                if (GELU) {
                    v0 = 0.5f * v0 * (1.f + erff(v0 * 0.70710678118654752f));
                    v1 = 0.5f * v1 * (1.f + erff(v1 * 0.70710678118654752f));
                }
                if (OUTF) {
                    float2 o; o.x = v0; o.y = v1;
                    *(float2*)(C + (size_t)m * N + n) = o;
                }
                if (OUTS1) {
                    *(__half2*)(Ch + (size_t)m * N + n) =
                        __halves2half2(__float2half_rn(v0), __float2half_rn(v1));
                }
                if (OUTT) {
                    const int bb = m >> 9, tt = m & (T - 1);
                    const int hh = n >> 6, cc = n & (HS - 1);
                    __half h0,l0,h1,l1;
                    split2h(v0,h0,l0); split2h(v1,h1,l1);
                    size_t o0 = (((size_t)bb * H + hh) * HS + cc) * T + tt;
                    Ch[o0] = h0; Cl[o0] = l0;
                    Ch[o0 + T] = h1; Cl[o0 + T] = l1;
                }
            }
        }
    }
}

// ===================== rel kernel: R = q . rel (dual-stream) ================
__global__ __launch_bounds__(256) void rel_kernel(const float* __restrict__ relp)
{
    const int t = blockIdx.x;
    const int h = blockIdx.y;
    const int tid = threadIdx.x;

    __shared__ float4 qs4[8 * 16];
    if (tid < 128) {
        int b = tid >> 4, c4 = tid & 15;
        qs4[tid] = *(const float4*)(g_q + ((size_t)(b * T + t)) * D + h * HS + c4 * 4);
    }
    __syncthreads();

    const int v0 = tid, v1 = tid + 256;
    const float4* relA = (const float4*)(relp + (((size_t)h * T + t) * T + v0) * HS);
    const float4* relB = (const float4*)(relp + (((size_t)h * T + t) * T + v1) * HS);
    float accA[8], accB[8];
    #pragma unroll
    for (int b = 0; b < 8; b++) { accA[b] = 0.f; accB[b] = 0.f; }
    #pragma unroll 4
    for (int c4 = 0; c4 < 16; c4++) {
        float4 ra = relA[c4];
        float4 rb = relB[c4];
        #pragma unroll
        for (int b = 0; b < 8; b++) {
            float4 q = qs4[b * 16 + c4];
            accA[b] = fmaf(q.x, ra.x, accA[b]);
            accA[b] = fmaf(q.y, ra.y, accA[b]);
            accA[b] = fmaf(q.z, ra.z, accA[b]);
            accA[b] = fmaf(q.w, ra.w, accA[b]);
            accB[b] = fmaf(q.x, rb.x, accB[b]);
            accB[b] = fmaf(q.y, rb.y, accB[b]);
            accB[b] = fmaf(q.z, rb.z, accB[b]);
            accB[b] = fmaf(q.w, rb.w, accB[b]);
        }
    }
    #pragma unroll
    for (int b = 0; b < 8; b++) {
        size_t base = (((size_t)(b * H + h)) * T + t) * T;
        g_rel[base + v0] = __float2half_rn(accA[b]);
        g_rel[base + v1] = __float2half_rn(accB[b]);
    }
}

// ===================== fused attention =====================
// CTA: (64 query rows, one bh). scores=q@(8k)^T+rel in smem fp32 -> softmax
// -> probs fp16 in smem (ldmatrix tile layout) -> out = P @ V.
static constexpr int FA_QB   = 0;        // q tiles: 4 x 5120 = 20480
static constexpr int FA_KB   = 20480;    // k8 tiles: 4 x 10240 (ends 61440)
static constexpr int FA_PB   = 0;        // probs: 16 chunks x 5120 = 81920 (reuses q/k)
static constexpr int FA_SC   = 81920;    // scores fp32 64x512 = 131072
static constexpr int FA_VB   = 81920;    // phase-3 V stages (reuses scores)
static constexpr int FA_VSTG = 10240;    // hi 5120 + lo 5120
static constexpr int FA_SMEM = 81920 + 131072;  // 212992

__global__ __launch_bounds__(256, 1) void fused_attn()
{
    extern __shared__ char sm[];
    const uint32_t smb = smem_to_u32(sm);
    const int tid = threadIdx.x;
    const int wid = tid >> 5, lane = tid & 31;
    const int warpM = wid & 1, warpN = wid >> 1;
    const int t0 = blockIdx.x * 64;
    const int bh = blockIdx.y;
    const int b = bh >> 3, h = bh & 7;

    // ---- load q tiles: 64 rows x (2 k-chunks) x hi/lo ----
    #pragma unroll
    for (int i = 0; i < 4; ++i) {
        int idx = tid + 256 * i;
        int tile = idx >> 8;            // 0: qh c0, 1: qh c1, 2: ql c0, 3: ql c1
        int r    = (idx >> 2) & 63;
        int u    = idx & 3;
        const __half* src = (tile < 2 ? g_qh : g_ql)
            + (size_t)(b * T + t0 + r) * D + h * HS + (tile & 1) * 32 + u * 8;
        cp16(smb + FA_QB + tile * 5120 + r * 80 + u * 16, src);
    }
    CP_COMMIT;

    const uint32_t a_off = FA_QB + (warpM * 32 + (lane & 15)) * 80 + (lane >> 4) * 16;
    const uint32_t b_off = FA_KB + (warpN * 32 + ((lane >> 4) << 3) + (lane & 7)) * 80 + ((lane >> 3) & 1) * 16;

    // ---- phase 1: scores (4 n-chunks of 128 cols) ----
    for (int nc = 0; nc < 4; ++nc) {
        #pragma unroll
        for (int i = 0; i < 8; ++i) {
            int idx = tid + 256 * i;
            int tile = idx >> 9;        // 0: kh c0, 1: kh c1, 2: kl c0, 3: kl c1
            int r    = (idx >> 2) & 127;
            int u    = idx & 3;
            const __half* src = (tile < 2 ? g_k8h : g_k8l)
                + (size_t)(b * T + nc * 128 + r) * D + h * HS + (tile & 1) * 32 + u * 8;
            cp16(smb + FA_KB + tile * 10240 + r * 80 + u * 16, src);
        }
        CP_COMMIT;
        CP_WAIT0;
        __syncthreads();

        float acc[2][4][4];
        #pragma unroll
        for (int i = 0; i < 2; i++)
            #pragma unroll
            for (int j = 0; j < 4; j++)
                #pragma unroll
                for (int r = 0; r < 4; r++) acc[i][j][r] = 0.f;

        #pragma unroll
        for (int kc = 0; kc < 2; ++kc) {
            #pragma unroll
            for (int ks = 0; ks < 2; ++ks) {
                uint32_t ahr[2][4], alr[2][4], bhr[2][4], blr[2][4];
                #pragma unroll
                for (int i = 0; i < 2; ++i) {
                    ldsm4(ahr[i], smb + a_off + kc * 5120 + i * (16*80) + ks * 32);
                    ldsm4(alr[i], smb + a_off + 10240 + kc * 5120 + i * (16*80) + ks * 32);
                }
                #pragma unroll
                for (int j = 0; j < 2; ++j) {
                    ldsm4(bhr[j], smb + b_off + kc * 10240 + j * (16*80) + ks * 32);
                    ldsm4(blr[j], smb + b_off + 20480 + kc * 10240 + j * (16*80) + ks * 32);
                }
                #pragma unroll
                for (int i = 0; i < 2; ++i)
                    #pragma unroll
                    for (int j = 0; j < 4; ++j) {
                        uint32_t bfh[2] = { bhr[j >> 1][(j & 1) * 2], bhr[j >> 1][(j & 1) * 2 + 1] };
                        uint32_t bfl[2] = { blr[j >> 1][(j & 1) * 2], blr[j >> 1][(j & 1) * 2 + 1] };
                        mma_f16(acc[i][j], ahr[i], bfh);
                        mma_f16(acc[i][j], ahr[i], bfl);
                        mma_f16(acc[i][j], alr[i], bfh);
                    }
            }
        }

        // add rel + store scores to smem
        const __half* Rb = g_rel + ((size_t)bh * T + t0) * T;
        #pragma unroll
        for (int i = 0; i < 2; ++i)
            #pragma unroll
            for (int j = 0; j < 4; ++j)
                #pragma unroll
                for (int rr = 0; rr < 2; ++rr) {
                    const int row = warpM * 32 + i * 16 + (lane >> 2) + rr * 8;
                    const int col = nc * 128 + warpN * 32 + j * 8 + (lane & 3) * 2;
                    __half2 rv = *(const __half2*)(Rb + (size_t)row * T + col);
                    float2 o;
                    o.x = acc[i][j][rr*2+0] + __half2float(rv.x);
                    o.y = acc[i][j][rr*2+1] + __half2float(rv.y);
                    *(float2*)(sm + FA_SC + row * 2048 + col * 4) = o;
                }
        __syncthreads();
    }

    // ---- phase 2: softmax (warp w: rows w*8..w*8+7), probs -> tile layout ----
    for (int rr = 0; rr < 8; ++rr) {
        const int r = wid * 8 + rr;
        const float4* srow = (const float4*)(sm + FA_SC + r * 2048);
        float4 v[4];
        float mx = -1e30f;
        #pragma unroll
        for (int j = 0; j < 4; ++j) {
            v[j] = srow[lane + 32 * j];
            mx = fmaxf(mx, fmaxf(fmaxf(v[j].x, v[j].y), fmaxf(v[j].z, v[j].w)));
        }
        #pragma unroll
        for (int o = 16; o > 0; o >>= 1) mx = fmaxf(mx, __shfl_xor_sync(0xffffffffu, mx, o));
        float s = 0.f;
        #pragma unroll
        for (int j = 0; j < 4; ++j) {
            v[j].x = __expf(v[j].x - mx); v[j].y = __expf(v[j].y - mx);
            v[j].z = __expf(v[j].z - mx); v[j].w = __expf(v[j].w - mx);
            s += v[j].x + v[j].y + v[j].z + v[j].w;
        }
        #pragma unroll
        for (int o = 16; o > 0; o >>= 1) s += __shfl_xor_sync(0xffffffffu, s, o);
        const float inv = 1.f / s;
        #pragma unroll
        for (int j = 0; j < 4; ++j) {
            const int col0 = (lane + 32 * j) * 4;
            const uint32_t off = FA_PB + (col0 >> 5) * 5120 + r * 80 + (col0 & 31) * 2;
            *(__half2*)(sm + off)     = __halves2half2(__float2half_rn(v[j].x * inv),
                                                       __float2half_rn(v[j].y * inv));
            *(__half2*)(sm + off + 4) = __halves2half2(__float2half_rn(v[j].z * inv),
                                                       __float2half_rn(v[j].w * inv));
        }
    }
    __syncthreads();

    // ---- phase 3: out = P @ V (K = 512, 16 chunks, V hi/lo pipelined) ----
    auto vload = [&](int c, int s) {
        const int r = tid >> 2, u = tid & 3;
        const size_t gsrc = (size_t)(bh * HS + r) * T + c * 32 + u * 8;
        cp16(smb + FA_VB + s * FA_VSTG + r * 80 + u * 16, g_vth + gsrc);
        cp16(smb + FA_VB + s * FA_VSTG + 5120 + r * 80 + u * 16, g_vtl + gsrc);
        CP_COMMIT;
    };
    vload(0, 0);
    vload(1, 1);

    float oac[2][2][4];
    #pragma unroll
    for (int i = 0; i < 2; i++)
        #pragma unroll
        for (int j = 0; j < 2; j++)
            #pragma unroll
            for (int r = 0; r < 4; r++) oac[i][j][r] = 0.f;

    const uint32_t pa_off = FA_PB + (warpM * 32 + (lane & 15)) * 80 + (lane >> 4) * 16;
    const uint32_t vb_off = (warpN * 16 + ((lane >> 4) << 3) + (lane & 7)) * 80 + ((lane >> 3) & 1) * 16;

    for (int c = 0; c < 16; ++c) {
        if (c + 1 < 16) { CP_WAIT1; } else { CP_WAIT0; }
        __syncthreads();
        if (c + 2 < 16) vload(c + 2, (c + 2) % 3);
        const uint32_t vb = smb + FA_VB + (c % 3) * FA_VSTG;
        #pragma unroll
        for (int ks = 0; ks < 2; ++ks) {
            uint32_t ar[2][4], vh4[4], vl4[4];
            #pragma unroll
            for (int i = 0; i < 2; ++i)
                ldsm4(ar[i], smb + pa_off + c * 5120 + i * (16*80) + ks * 32);
            ldsm4(vh4, vb + vb_off + ks * 32);
            ldsm4(vl4, vb + 5120 + vb_off + ks * 32);
            #pragma unroll
            for (int i = 0; i < 2; ++i)
                #pragma unroll
                for (int j = 0; j < 2; ++j) {
                    uint32_t bfh[2] = { vh4[j * 2], vh4[j * 2 + 1] };
                    uint32_t bfl[2] = { vl4[j * 2], vl4[j * 2 + 1] };
                    mma_f16(oac[i][j], ar[i], bfh);
                    mma_f16(oac[i][j], ar[i], bfl);
                }
        }
    }

    // epilogue: write attention output (fp16 single)
    #pragma unroll
    for (int i = 0; i < 2; ++i)
        #pragma unroll
        for (int j = 0; j < 2; ++j)
            #pragma unroll
            for (int rr = 0; rr < 2; ++rr) {
                const int m = t0 + warpM * 32 + i * 16 + (lane >> 2) + rr * 8;
                const int cc = warpN * 16 + j * 8 + (lane & 3) * 2;
                *(__half2*)(g_att + (size_t)(b * T + m) * D + h * HS + cc) =
                    __halves2half2(__float2half_rn(oac[i][j][rr*2+0]),
                                   __float2half_rn(oac[i][j][rr*2+1]));
            }
}

// ===================== launch ==============================================
extern "C" void kernel_launch(void* const* d_in, const int* in_sizes, int n_in,
                              void* d_out, int out_size)
{
    (void)in_sizes; (void)n_in; (void)out_size;
    const float* src    = (const float*)d_in[0];
    const float* norm_w = (const float*)d_in[1];
    const float* Wq     = (const float*)d_in[2];
    const float* bq     = (const float*)d_in[3];
    const float* Wk     = (const float*)d_in[4];
    const float* bk     = (const float*)d_in[5];
    const float* Wv     = (const float*)d_in[6];
    const float* bv     = (const float*)d_in[7];
    const float* relp   = (const float*)d_in[8];
    const float* proj_w = (const float*)d_in[9];
    const float* proj_b = (const float*)d_in[10];
    const float* ff_w1  = (const float*)d_in[11];
    const float* ff_b1  = (const float*)d_in[12];
    const float* ff_w2  = (const float*)d_in[13];
    const float* ff_b2  = (const float*)d_in[14];
    float* out = (float*)d_out;

    float *px, *psrc2, *py;
    __half *pxh, *pxl, *pyh, *pyl, *pvth, *pvtl, *patt, *phid;
    __half *ppwh, *ppwl, *pf1h, *pf1l, *pf2h, *pf2l, *pw3h, *pw3l;
    cudaGetSymbolAddress((void**)&px,    g_x);
    cudaGetSymbolAddress((void**)&psrc2, g_src2);
    cudaGetSymbolAddress((void**)&py,    g_y);
    cudaGetSymbolAddress((void**)&pxh,   g_xh);
    cudaGetSymbolAddress((void**)&pxl,   g_xl);
    cudaGetSymbolAddress((void**)&pyh,   g_yh);
    cudaGetSymbolAddress((void**)&pyl,   g_yl);
    cudaGetSymbolAddress((void**)&pvth,  g_vth);
    cudaGetSymbolAddress((void**)&pvtl,  g_vtl);
    cudaGetSymbolAddress((void**)&patt,  g_att);
    cudaGetSymbolAddress((void**)&phid,  g_hid);
    cudaGetSymbolAddress((void**)&pw3h,  g_w3h);
    cudaGetSymbolAddress((void**)&pw3l,  g_w3l);
    cudaGetSymbolAddress((void**)&ppwh,  g_pwh);
    cudaGetSymbolAddress((void**)&ppwl,  g_pwl);
    cudaGetSymbolAddress((void**)&pf1h,  g_f1h);
    cudaGetSymbolAddress((void**)&pf1l,  g_f1l);
    cudaGetSymbolAddress((void**)&pf2h,  g_f2h);
    cudaGetSymbolAddress((void**)&pf2l,  g_f2l);

    cudaFuncSetAttribute(gemm_qk, cudaFuncAttributeMaxDynamicSharedMemorySize, G3_SMEM);
    cudaFuncSetAttribute(gemm2<false,false,false,false,true>,  cudaFuncAttributeMaxDynamicSharedMemorySize, G2_SMEM);
    cudaFuncSetAttribute(gemm2<true, false,true, false,false>, cudaFuncAttributeMaxDynamicSharedMemorySize, G2_SMEM);
    cudaFuncSetAttribute(gemm2<false,true, false,true, false>, cudaFuncAttributeMaxDynamicSharedMemorySize, G2_SMEM);
    cudaFuncSetAttribute(fused_attn, cudaFuncAttributeMaxDynamicSharedMemorySize, FA_SMEM);

    // weight prep
    wsplit_qkv_t<<<dim3(D/32, HS/32, 24), 256>>>(Wq, Wk, Wv);
    wsplit_t<<<dim3(D/32, D/32),  256>>>(proj_w, ppwh, ppwl, D, D);
    wsplit_t<<<dim3(FF/32, D/32), 256>>>(ff_w1, pf1h, pf1l, D, FF);
    wsplit_t<<<dim3(D/32, FF/32), 256>>>(ff_w2, pf2h, pf2l, FF, D);

    // x = rmsnorm(src)
    rmsnorm_kernel<<<BT, 128>>>(src, norm_w, px, pxh, pxl);

    // q (fp32 + hi/lo) and k8 (hi/lo) in one launch
    gemm_qk<<<dim3(D/128, BT/128, 2), 256, G3_SMEM>>>(bq, bk);
    // v: transposed hi/lo fp16 (2-product)
    gemm2<false,false,false,false,true><<<dim3(D/128, BT/128), 256, G2_SMEM>>>(
        pxh, pw3h + 2*D*D, pw3l + 2*D*D, bv, nullptr, nullptr, pvth, pvtl, BT, D, D, 1.f);

    // attention
    rel_kernel<<<dim3(T, H), 256>>>(relp);
    fused_attn<<<dim3(T/64, BATCH*H), 256, FA_SMEM>>>();

    // src2 = x + att @ proj_w + proj_b
    gemm2<true,false,true,false,false><<<dim3(D/128, BT/128), 256, G2_SMEM>>>(
        patt, ppwh, ppwl, proj_b, px, psrc2, nullptr, nullptr, BT, D, D, 1.f);

    // y = rmsnorm(src2)
    rmsnorm_kernel<<<BT, 128>>>(psrc2, norm_w, py, pyh, pyl);

    // h = gelu(y @ ff_w1 + ff_b1)
    gemm2<false,true,false,true,false><<<dim3(FF/128, BT/128), 256, G2_SMEM>>>(
        pyh, pf1h, pf1l, ff_b1, nullptr, nullptr, phid, nullptr, BT, FF, D, 1.f);

    // out = y + h @ ff_w2 + ff_b2
    gemm2<true,false,true,false,false><<<dim3(D/128, BT/128), 256, G2_SMEM>>>(
        phid, pf2h, pf2l, ff_b2, py, out, nullptr, nullptr, BT, D, FF, 1.f);
}

// round 8
// speedup vs baseline: 4.2864x; 1.1375x over previous
#include <cuda_runtime.h>
#include <cuda_fp16.h>
#include <math.h>
#include <stdint.h>

#define BATCH 8
#define T 512
#define D 512
#define H 8
#define HS 64
#define BT (BATCH*T)     // 4096
#define FF 2048

// ===================== device scratch =====================
__device__ __align__(16) float g_x[BT*D];
__device__ __align__(16) float g_q[BT*D];
__device__ __align__(16) float g_src2[BT*D];
__device__ __align__(16) float g_y[BT*D];
__device__ __align__(16) __half g_rel[BATCH*H*T*T];     // 32MB
__device__ __align__(16) __half g_xh[BT*D], g_xl[BT*D];
__device__ __align__(16) __half g_yh[BT*D], g_yl[BT*D];
__device__ __align__(16) __half g_qh[BT*D], g_ql[BT*D];
__device__ __align__(16) __half g_k8h[BT*D], g_k8l[BT*D];
__device__ __align__(16) __half g_vth[BATCH*H*HS*T];
__device__ __align__(16) __half g_att[BT*D];
__device__ __align__(16) __half g_hid[BT*FF];
__device__ __align__(16) __half g_w3h[3*D*D], g_w3l[3*D*D];
__device__ __align__(16) __half g_pwh[D*D],  g_pwl[D*D];
__device__ __align__(16) __half g_f1h[FF*D], g_f1l[FF*D];
__device__ __align__(16) __half g_f2h[D*FF], g_f2l[D*FF];

__device__ __forceinline__ void split2h(float v, __half& h, __half& l) {
    h = __float2half_rn(v);
    l = __float2half_rn(v - __half2float(h));
}

// ===================== primitives =====================
__device__ __forceinline__ void mma_f16(float* d, const uint32_t* a, const uint32_t* b) {
    asm volatile(
        "mma.sync.aligned.m16n8k16.row.col.f32.f16.f16.f32 "
        "{%0,%1,%2,%3}, {%4,%5,%6,%7}, {%8,%9}, {%0,%1,%2,%3};"
        : "+f"(d[0]), "+f"(d[1]), "+f"(d[2]), "+f"(d[3])
        : "r"(a[0]), "r"(a[1]), "r"(a[2]), "r"(a[3]), "r"(b[0]), "r"(b[1]));
}
__device__ __forceinline__ void ldsm4(uint32_t* r, uint32_t addr) {
    asm volatile("ldmatrix.sync.aligned.m8n8.x4.shared.b16 {%0,%1,%2,%3}, [%4];"
        : "=r"(r[0]), "=r"(r[1]), "=r"(r[2]), "=r"(r[3]) : "r"(addr));
}
__device__ __forceinline__ uint32_t smem_to_u32(const void* p) {
    uint32_t a;
    asm("{ .reg .u64 t; cvta.to.shared.u64 t, %1; cvt.u32.u64 %0, t; }" : "=r"(a) : "l"(p));
    return a;
}
__device__ __forceinline__ void cp16(uint32_t s, const void* g) {
    asm volatile("{.reg .u64 gp; cvta.to.global.u64 gp, %1; cp.async.cg.shared.global [%0], [gp], 16;}"
        :: "r"(s), "l"(g) : "memory");
}
#define CP_COMMIT asm volatile("cp.async.commit_group;" ::: "memory")
#define CP_WAIT1  asm volatile("cp.async.wait_group 1;" ::: "memory")
#define CP_WAIT0  asm volatile("cp.async.wait_group 0;" ::: "memory")

// ===================== weight prep (coalesced transpose) =====================
__global__ __launch_bounds__(256) void wsplit_t(const float* __restrict__ W,
                                                __half* __restrict__ Wh, __half* __restrict__ Wl,
                                                int K, int N)
{
    __shared__ float tile[32][33];
    const int n0 = blockIdx.x * 32, k0 = blockIdx.y * 32;
    const int tx = threadIdx.x & 31, ty = threadIdx.x >> 5;
    #pragma unroll
    for (int i = 0; i < 32; i += 8)
        tile[ty + i][tx] = W[(size_t)(k0 + ty + i) * N + n0 + tx];
    __syncthreads();
    #pragma unroll
    for (int i = 0; i < 32; i += 8) {
        float v = tile[tx][ty + i];
        __half h, l; split2h(v, h, l);
        size_t o = (size_t)(n0 + ty + i) * K + k0 + tx;
        Wh[o] = h; Wl[o] = l;
    }
}

__global__ __launch_bounds__(256) void wsplit_qkv_t(const float* __restrict__ Wq,
                                                    const float* __restrict__ Wk,
                                                    const float* __restrict__ Wv)
{
    __shared__ float tile[32][33];
    const int mat = blockIdx.z >> 3, h = blockIdx.z & 7;
    const int c0 = blockIdx.y * 32, d0 = blockIdx.x * 32;
    const int tx = threadIdx.x & 31, ty = threadIdx.x >> 5;
    const float* W = (mat == 0) ? Wq : (mat == 1) ? Wk : Wv;
    #pragma unroll
    for (int i = 0; i < 32; i += 8)
        tile[ty + i][tx] = W[((size_t)h * D + d0 + ty + i) * HS + c0 + tx];
    __syncthreads();
    #pragma unroll
    for (int i = 0; i < 32; i += 8) {
        float v = tile[tx][ty + i];
        __half hh, ll; split2h(v, hh, ll);
        size_t o = (size_t)mat * D * D + (size_t)(h * HS + c0 + ty + i) * D + d0 + tx;
        g_w3h[o] = hh; g_w3l[o] = ll;
    }
}

// ===================== rmsnorm =====================
__global__ __launch_bounds__(128) void rmsnorm_kernel(
    const float* __restrict__ in, const float* __restrict__ w,
    float* __restrict__ out, __half* __restrict__ outh, __half* __restrict__ outl)
{
    int row = blockIdx.x;
    int tid = threadIdx.x;
    const float4 v = ((const float4*)(in + (size_t)row * D))[tid];
    float ss = v.x*v.x + v.y*v.y + v.z*v.z + v.w*v.w;
    #pragma unroll
    for (int o = 16; o > 0; o >>= 1) ss += __shfl_xor_sync(0xffffffffu, ss, o);
    __shared__ float ws[4];
    if ((tid & 31) == 0) ws[tid >> 5] = ss;
    __syncthreads();
    float total = ws[0] + ws[1] + ws[2] + ws[3];
    float r = rsqrtf(total * (1.0f / (float)D) + 1e-6f);
    const float4 wv = ((const float4*)w)[tid];
    float4 o;
    o.x = v.x * r * wv.x; o.y = v.y * r * wv.y;
    o.z = v.z * r * wv.z; o.w = v.w * r * wv.w;
    ((float4*)(out + (size_t)row * D))[tid] = o;
    __half h0,l0,h1,l1,h2,l2,h3,l3;
    split2h(o.x,h0,l0); split2h(o.y,h1,l1); split2h(o.z,h2,l2); split2h(o.w,h3,l3);
    size_t base = (size_t)row * D + tid * 4;
    *(__half2*)(outh + base)     = __halves2half2(h0,h1);
    *(__half2*)(outh + base + 2) = __halves2half2(h2,h3);
    *(__half2*)(outl + base)     = __halves2half2(l0,l1);
    *(__half2*)(outl + base + 2) = __halves2half2(l2,l3);
}

// ===================== tile constants =====================
static constexpr int TROW  = 80;
static constexpr int TILEB = 128 * TROW;      // 10240
static constexpr int G1_SMEM = 3 * 2 * TILEB; // 61440
static constexpr int G2_SMEM = 3 * 3 * TILEB; // 92160
static constexpr int G3_STG  = 4 * TILEB;     // 40960
static constexpr int G3_SMEM = 3 * G3_STG;    // 122880

// ===================== merged q/k GEMM (3-product, z selects) ==============
__global__ __launch_bounds__(256, 1) void gemm_qk(
    const float* __restrict__ bq, const float* __restrict__ bk)
{
    extern __shared__ char sm[];
    const int z = blockIdx.z;               // 0: q, 1: k8
    const __half* Ah = g_xh;
    const __half* Al = g_xl;
    const __half* Bh = g_w3h + (size_t)z * D * D;
    const __half* Bl = g_w3l + (size_t)z * D * D;
    const float* bias = z ? bk : bq;
    const float osc = z ? 8.f : 1.f;
    const int K = D, N = D;

    const int tid  = threadIdx.x;
    const int wid  = tid >> 5, lane = tid & 31;
    const int warpM = wid & 1, warpN = wid >> 1;
    const int bm = blockIdx.y * 128, bn = blockIdx.x * 128;
    const uint32_t smb = smem_to_u32(sm);

    const int lrow   = tid >> 2;
    const int lchunk = tid & 3;
    const int soff   = lrow * TROW + lchunk * 16;
    const int a_off = (warpM * 64 + (lane & 15)) * TROW + (lane >> 4) * 16;
    const int b_off = (warpN * 32 + ((lane >> 4) << 3) + (lane & 7)) * TROW + ((lane >> 3) & 1) * 16;

    float acc[4][4][4];
    #pragma unroll
    for (int i = 0; i < 4; i++)
        #pragma unroll
        for (int j = 0; j < 4; j++)
            #pragma unroll
            for (int r = 0; r < 4; r++) acc[i][j][r] = 0.f;

    const int nch = K >> 5;
    auto issue = [&](int c, int s) {
        const int k0 = c << 5;
        const uint32_t st = smb + s * G3_STG;
        const __half* pa  = Ah + (size_t)(bm + lrow) * K + k0 + lchunk * 8;
        const __half* pal = Al + (size_t)(bm + lrow) * K + k0 + lchunk * 8;
        const __half* pb  = Bh + (size_t)(bn + lrow) * K + k0 + lchunk * 8;
        const __half* pbl = Bl + (size_t)(bn + lrow) * K + k0 + lchunk * 8;
        cp16(st + soff, pa);            cp16(st + soff + 64*TROW, pa + (size_t)64*K);
        cp16(st + TILEB + soff, pal);   cp16(st + TILEB + soff + 64*TROW, pal + (size_t)64*K);
        cp16(st + 2*TILEB + soff, pb);  cp16(st + 2*TILEB + soff + 64*TROW, pb + (size_t)64*K);
        cp16(st + 3*TILEB + soff, pbl); cp16(st + 3*TILEB + soff + 64*TROW, pbl + (size_t)64*K);
        CP_COMMIT;
    };
    issue(0, 0);
    issue(1, 1);

    for (int c = 0; c < nch; ++c) {
        if (c + 1 < nch) { CP_WAIT1; } else { CP_WAIT0; }
        __syncthreads();
        if (c + 2 < nch) issue(c + 2, (c + 2) % 3);
        const uint32_t sb = smb + (c % 3) * G3_STG;
        #pragma unroll
        for (int ks = 0; ks < 2; ++ks) {
            uint32_t ahr[4][4], alr[4][4], bhr[2][4], blr[2][4];
            #pragma unroll
            for (int i = 0; i < 4; ++i) {
                ldsm4(ahr[i], sb + a_off + i * (16 * TROW) + ks * 32);
                ldsm4(alr[i], sb + TILEB + a_off + i * (16 * TROW) + ks * 32);
            }
            #pragma unroll
            for (int j = 0; j < 2; ++j) {
                ldsm4(bhr[j], sb + 2*TILEB + b_off + j * (16 * TROW) + ks * 32);
                ldsm4(blr[j], sb + 3*TILEB + b_off + j * (16 * TROW) + ks * 32);
            }
            #pragma unroll
            for (int i = 0; i < 4; ++i)
                #pragma unroll
                for (int j = 0; j < 4; ++j) {
                    uint32_t bfh[2] = { bhr[j >> 1][(j & 1) * 2], bhr[j >> 1][(j & 1) * 2 + 1] };
                    uint32_t bfl[2] = { blr[j >> 1][(j & 1) * 2], blr[j >> 1][(j & 1) * 2 + 1] };
                    mma_f16(acc[i][j], ahr[i], bfh);
                    mma_f16(acc[i][j], ahr[i], bfl);
                    mma_f16(acc[i][j], alr[i], bfh);
                }
        }
    }

    #pragma unroll
    for (int i = 0; i < 4; ++i) {
        const int m0 = bm + warpM * 64 + i * 16 + (lane >> 2);
        #pragma unroll
        for (int j = 0; j < 4; ++j) {
            const int n = bn + warpN * 32 + j * 8 + (lane & 3) * 2;
            const float b0 = bias[n], b1 = bias[n + 1];
            #pragma unroll
            for (int rr = 0; rr < 2; ++rr) {
                const int m = m0 + rr * 8;
                float v0 = (acc[i][j][rr*2+0] + b0) * osc;
                float v1 = (acc[i][j][rr*2+1] + b1) * osc;
                __half h0,l0,h1,l1;
                split2h(v0,h0,l0); split2h(v1,h1,l1);
                if (z == 0) {
                    float2 o; o.x = v0; o.y = v1;
                    *(float2*)(g_q + (size_t)m * N + n) = o;
                    *(__half2*)(g_qh + (size_t)m * N + n) = __halves2half2(h0,h1);
                    *(__half2*)(g_ql + (size_t)m * N + n) = __halves2half2(l0,l1);
                } else {
                    *(__half2*)(g_k8h + (size_t)m * N + n) = __halves2half2(h0,h1);
                    *(__half2*)(g_k8l + (size_t)m * N + n) = __halves2half2(l0,l1);
                }
            }
        }
    }
}

// ===================== gemmN: NPROD-product (A single, B hi[/lo]) ==========
template<int NPROD, bool RESID, bool GELU, bool OUTF, bool OUTS1, bool OUTT>
__global__ __launch_bounds__(256, 2) void gemmN(
    const __half* __restrict__ A,
    const __half* __restrict__ Bh, const __half* __restrict__ Bl,
    const float* __restrict__ bias, const float* __restrict__ R,
    float* __restrict__ C, __half* __restrict__ Ch,
    int M, int N, int K, float osc)
{
    extern __shared__ char sm[];
    constexpr int STGB = (1 + NPROD) * TILEB;
    const int tid  = threadIdx.x;
    const int wid  = tid >> 5, lane = tid & 31;
    const int warpM = wid & 1, warpN = wid >> 1;
    const int bm = blockIdx.y * 128, bn = blockIdx.x * 128;
    const uint32_t smb = smem_to_u32(sm);

    const int lrow   = tid >> 2;
    const int lchunk = tid & 3;
    const int soff   = lrow * TROW + lchunk * 16;
    const int a_off = (warpM * 64 + (lane & 15)) * TROW + (lane >> 4) * 16;
    const int b_off = (warpN * 32 + ((lane >> 4) << 3) + (lane & 7)) * TROW + ((lane >> 3) & 1) * 16;

    float acc[4][4][4];
    #pragma unroll
    for (int i = 0; i < 4; i++)
        #pragma unroll
        for (int j = 0; j < 4; j++)
            #pragma unroll
            for (int r = 0; r < 4; r++) acc[i][j][r] = 0.f;

    const int nch = K >> 5;
    auto issue = [&](int c, int s) {
        const int k0 = c << 5;
        const uint32_t st = smb + s * STGB;
        const __half* pa  = A  + (size_t)(bm + lrow) * K + k0 + lchunk * 8;
        const __half* pb  = Bh + (size_t)(bn + lrow) * K + k0 + lchunk * 8;
        cp16(st + soff, pa);            cp16(st + soff + 64*TROW, pa + (size_t)64*K);
        cp16(st + TILEB + soff, pb);    cp16(st + TILEB + soff + 64*TROW, pb + (size_t)64*K);
        if (NPROD == 2) {
            const __half* pbl = Bl + (size_t)(bn + lrow) * K + k0 + lchunk * 8;
            cp16(st + 2*TILEB + soff, pbl);
            cp16(st + 2*TILEB + soff + 64*TROW, pbl + (size_t)64*K);
        }
        CP_COMMIT;
    };
    issue(0, 0);
    if (nch > 1) issue(1, 1);

    for (int c = 0; c < nch; ++c) {
        if (c + 1 < nch) { CP_WAIT1; } else { CP_WAIT0; }
        __syncthreads();
        if (c + 2 < nch) issue(c + 2, (c + 2) % 3);
        const uint32_t sb = smb + (c % 3) * STGB;
        #pragma unroll
        for (int ks = 0; ks < 2; ++ks) {
            uint32_t ar[4][4], bhr[2][4], blr[2][4];
            #pragma unroll
            for (int i = 0; i < 4; ++i)
                ldsm4(ar[i], sb + a_off + i * (16 * TROW) + ks * 32);
            #pragma unroll
            for (int j = 0; j < 2; ++j) {
                ldsm4(bhr[j], sb + TILEB + b_off + j * (16 * TROW) + ks * 32);
                if (NPROD == 2)
                    ldsm4(blr[j], sb + 2*TILEB + b_off + j * (16 * TROW) + ks * 32);
            }
            #pragma unroll
            for (int i = 0; i < 4; ++i)
                #pragma unroll
                for (int j = 0; j < 4; ++j) {
                    uint32_t bfh[2] = { bhr[j >> 1][(j & 1) * 2], bhr[j >> 1][(j & 1) * 2 + 1] };
                    mma_f16(acc[i][j], ar[i], bfh);
                    if (NPROD == 2) {
                        uint32_t bfl[2] = { blr[j >> 1][(j & 1) * 2], blr[j >> 1][(j & 1) * 2 + 1] };
                        mma_f16(acc[i][j], ar[i], bfl);
                    }
                }
        }
    }

    #pragma unroll
    for (int i = 0; i < 4; ++i) {
        const int m0 = bm + warpM * 64 + i * 16 + (lane >> 2);
        #pragma unroll
        for (int j = 0; j < 4; ++j) {
            const int n = bn + warpN * 32 + j * 8 + (lane & 3) * 2;
            const float b0 = bias[n], b1 = bias[n + 1];
            #pragma unroll
            for (int rr = 0; rr < 2; ++rr) {
                const int m = m0 + rr * 8;
                float v0 = acc[i][j][rr*2+0] + b0;
                float v1 = acc[i][j][rr*2+1] + b1;
                if (RESID) {
                    const float2 rv = *(const float2*)(R + (size_t)m * N + n);
                    v0 += rv.x; v1 += rv.y;
                }
                v0 *= osc; v1 *= osc;
                if (GELU) {
                    v0 = 0.5f * v0 * (1.f + erff(v0 * 0.70710678118654752f));
                    v1 = 0.5f * v1 * (1.f + erff(v1 * 0.70710678118654752f));
                }
                if (OUTF) {
                    float2 o; o.x = v0; o.y = v1;
                    *(float2*)(C + (size_t)m * N + n) = o;
                }
                if (OUTS1) {
                    *(__half2*)(Ch + (size_t)m * N + n) =
                        __halves2half2(__float2half_rn(v0), __float2half_rn(v1));
                }
                if (OUTT) {
                    const int bb = m >> 9, tt = m & (T - 1);
                    const int hh = n >> 6, cc = n & (HS - 1);
                    size_t o0 = (((size_t)bb * H + hh) * HS + cc) * T + tt;
                    Ch[o0]     = __float2half_rn(v0);
                    Ch[o0 + T] = __float2half_rn(v1);
                }
            }
        }
    }
}

// ===================== rel kernel: R = q . rel (dual-stream) ================
__global__ __launch_bounds__(256) void rel_kernel(const float* __restrict__ relp)
{
    const int t = blockIdx.x;
    const int h = blockIdx.y;
    const int tid = threadIdx.x;

    __shared__ float4 qs4[8 * 16];
    if (tid < 128) {
        int b = tid >> 4, c4 = tid & 15;
        qs4[tid] = *(const float4*)(g_q + ((size_t)(b * T + t)) * D + h * HS + c4 * 4);
    }
    __syncthreads();

    const int v0 = tid, v1 = tid + 256;
    const float4* relA = (const float4*)(relp + (((size_t)h * T + t) * T + v0) * HS);
    const float4* relB = (const float4*)(relp + (((size_t)h * T + t) * T + v1) * HS);
    float accA[8], accB[8];
    #pragma unroll
    for (int b = 0; b < 8; b++) { accA[b] = 0.f; accB[b] = 0.f; }
    #pragma unroll 8
    for (int c4 = 0; c4 < 16; c4++) {
        float4 ra = relA[c4];
        float4 rb = relB[c4];
        #pragma unroll
        for (int b = 0; b < 8; b++) {
            float4 q = qs4[b * 16 + c4];
            accA[b] = fmaf(q.x, ra.x, accA[b]);
            accA[b] = fmaf(q.y, ra.y, accA[b]);
            accA[b] = fmaf(q.z, ra.z, accA[b]);
            accA[b] = fmaf(q.w, ra.w, accA[b]);
            accB[b] = fmaf(q.x, rb.x, accB[b]);
            accB[b] = fmaf(q.y, rb.y, accB[b]);
            accB[b] = fmaf(q.z, rb.z, accB[b]);
            accB[b] = fmaf(q.w, rb.w, accB[b]);
        }
    }
    #pragma unroll
    for (int b = 0; b < 8; b++) {
        size_t base = (((size_t)(b * H + h)) * T + t) * T;
        g_rel[base + v0] = __float2half_rn(accA[b]);
        g_rel[base + v1] = __float2half_rn(accB[b]);
    }
}

// ===================== fused attention =====================
// CTA: (64 query rows, one bh). scores=q@(8k)^T+rel in smem fp32 -> softmax
// -> probs fp16 in smem (ldmatrix tile layout) -> out = P @ V (V single fp16).
static constexpr int FA_QB   = 0;        // q tiles: 4 x 5120 = 20480
static constexpr int FA_KB   = 20480;    // k8 tiles: 4 x 10240 (ends 61440)
static constexpr int FA_PB   = 0;        // probs: 16 chunks x 5120 = 81920 (reuses q/k)
static constexpr int FA_SC   = 81920;    // scores fp32 64x512 = 131072
static constexpr int FA_VB   = 81920;    // phase-3 V stages (reuses scores)
static constexpr int FA_VSTG = 5120;     // V hi only
static constexpr int FA_SMEM = 81920 + 131072;  // 212992

__global__ __launch_bounds__(256, 1) void fused_attn()
{
    extern __shared__ char sm[];
    const uint32_t smb = smem_to_u32(sm);
    const int tid = threadIdx.x;
    const int wid = tid >> 5, lane = tid & 31;
    const int warpM = wid & 1, warpN = wid >> 1;
    const int t0 = blockIdx.x * 64;
    const int bh = blockIdx.y;
    const int b = bh >> 3, h = bh & 7;

    // ---- load q tiles: 64 rows x (2 k-chunks) x hi/lo ----
    #pragma unroll
    for (int i = 0; i < 4; ++i) {
        int idx = tid + 256 * i;
        int tile = idx >> 8;            // 0: qh c0, 1: qh c1, 2: ql c0, 3: ql c1
        int r    = (idx >> 2) & 63;
        int u    = idx & 3;
        const __half* src = (tile < 2 ? g_qh : g_ql)
            + (size_t)(b * T + t0 + r) * D + h * HS + (tile & 1) * 32 + u * 8;
        cp16(smb + FA_QB + tile * 5120 + r * 80 + u * 16, src);
    }
    CP_COMMIT;

    const uint32_t a_off = FA_QB + (warpM * 32 + (lane & 15)) * 80 + (lane >> 4) * 16;
    const uint32_t b_off = FA_KB + (warpN * 32 + ((lane >> 4) << 3) + (lane & 7)) * 80 + ((lane >> 3) & 1) * 16;

    // ---- phase 1: scores (4 n-chunks of 128 cols) ----
    for (int nc = 0; nc < 4; ++nc) {
        #pragma unroll
        for (int i = 0; i < 8; ++i) {
            int idx = tid + 256 * i;
            int tile = idx >> 9;        // 0: kh c0, 1: kh c1, 2: kl c0, 3: kl c1
            int r    = (idx >> 2) & 127;
            int u    = idx & 3;
            const __half* src = (tile < 2 ? g_k8h : g_k8l)
                + (size_t)(b * T + nc * 128 + r) * D + h * HS + (tile & 1) * 32 + u * 8;
            cp16(smb + FA_KB + tile * 10240 + r * 80 + u * 16, src);
        }
        CP_COMMIT;
        CP_WAIT0;
        __syncthreads();

        float acc[2][4][4];
        #pragma unroll
        for (int i = 0; i < 2; i++)
            #pragma unroll
            for (int j = 0; j < 4; j++)
                #pragma unroll
                for (int r = 0; r < 4; r++) acc[i][j][r] = 0.f;

        #pragma unroll
        for (int kc = 0; kc < 2; ++kc) {
            #pragma unroll
            for (int ks = 0; ks < 2; ++ks) {
                uint32_t ahr[2][4], alr[2][4], bhr[2][4], blr[2][4];
                #pragma unroll
                for (int i = 0; i < 2; ++i) {
                    ldsm4(ahr[i], smb + a_off + kc * 5120 + i * (16*80) + ks * 32);
                    ldsm4(alr[i], smb + a_off + 10240 + kc * 5120 + i * (16*80) + ks * 32);
                }
                #pragma unroll
                for (int j = 0; j < 2; ++j) {
                    ldsm4(bhr[j], smb + b_off + kc * 10240 + j * (16*80) + ks * 32);
                    ldsm4(blr[j], smb + b_off + 20480 + kc * 10240 + j * (16*80) + ks * 32);
                }
                #pragma unroll
                for (int i = 0; i < 2; ++i)
                    #pragma unroll
                    for (int j = 0; j < 4; ++j) {
                        uint32_t bfh[2] = { bhr[j >> 1][(j & 1) * 2], bhr[j >> 1][(j & 1) * 2 + 1] };
                        uint32_t bfl[2] = { blr[j >> 1][(j & 1) * 2], blr[j >> 1][(j & 1) * 2 + 1] };
                        mma_f16(acc[i][j], ahr[i], bfh);
                        mma_f16(acc[i][j], ahr[i], bfl);
                        mma_f16(acc[i][j], alr[i], bfh);
                    }
            }
        }

        // add rel + store scores to smem
        const __half* Rb = g_rel + ((size_t)bh * T + t0) * T;
        #pragma unroll
        for (int i = 0; i < 2; ++i)
            #pragma unroll
            for (int j = 0; j < 4; ++j)
                #pragma unroll
                for (int rr = 0; rr < 2; ++rr) {
                    const int row = warpM * 32 + i * 16 + (lane >> 2) + rr * 8;
                    const int col = nc * 128 + warpN * 32 + j * 8 + (lane & 3) * 2;
                    __half2 rv = *(const __half2*)(Rb + (size_t)row * T + col);
                    float2 o;
                    o.x = acc[i][j][rr*2+0] + __half2float(rv.x);
                    o.y = acc[i][j][rr*2+1] + __half2float(rv.y);
                    *(float2*)(sm + FA_SC + row * 2048 + col * 4) = o;
                }
        __syncthreads();
    }

    // ---- phase 2: softmax (warp w: rows w*8..w*8+7), probs -> tile layout ----
    for (int rr = 0; rr < 8; ++rr) {
        const int r = wid * 8 + rr;
        const float4* srow = (const float4*)(sm + FA_SC + r * 2048);
        float4 v[4];
        float mx = -1e30f;
        #pragma unroll
        for (int j = 0; j < 4; ++j) {
            v[j] = srow[lane + 32 * j];
            mx = fmaxf(mx, fmaxf(fmaxf(v[j].x, v[j].y), fmaxf(v[j].z, v[j].w)));
        }
        #pragma unroll
        for (int o = 16; o > 0; o >>= 1) mx = fmaxf(mx, __shfl_xor_sync(0xffffffffu, mx, o));
        float s = 0.f;
        #pragma unroll
        for (int j = 0; j < 4; ++j) {
            v[j].x = __expf(v[j].x - mx); v[j].y = __expf(v[j].y - mx);
            v[j].z = __expf(v[j].z - mx); v[j].w = __expf(v[j].w - mx);
            s += v[j].x + v[j].y + v[j].z + v[j].w;
        }
        #pragma unroll
        for (int o = 16; o > 0; o >>= 1) s += __shfl_xor_sync(0xffffffffu, s, o);
        const float inv = 1.f / s;
        #pragma unroll
        for (int j = 0; j < 4; ++j) {
            const int col0 = (lane + 32 * j) * 4;
            const uint32_t off = FA_PB + (col0 >> 5) * 5120 + r * 80 + (col0 & 31) * 2;
            *(__half2*)(sm + off)     = __halves2half2(__float2half_rn(v[j].x * inv),
                                                       __float2half_rn(v[j].y * inv));
            *(__half2*)(sm + off + 4) = __halves2half2(__float2half_rn(v[j].z * inv),
                                                       __float2half_rn(v[j].w * inv));
        }
    }
    __syncthreads();

    // ---- phase 3: out = P @ V (K = 512, 16 chunks, V single, pipelined) ----
    auto vload = [&](int c, int s) {
        const int r = tid >> 2, u = tid & 3;
        const size_t gsrc = (size_t)(bh * HS + r) * T + c * 32 + u * 8;
        cp16(smb + FA_VB + s * FA_VSTG + r * 80 + u * 16, g_vth + gsrc);
        CP_COMMIT;
    };
    vload(0, 0);
    vload(1, 1);

    float oac[2][2][4];
    #pragma unroll
    for (int i = 0; i < 2; i++)
        #pragma unroll
        for (int j = 0; j < 2; j++)
            #pragma unroll
            for (int r = 0; r < 4; r++) oac[i][j][r] = 0.f;

    const uint32_t pa_off = FA_PB + (warpM * 32 + (lane & 15)) * 80 + (lane >> 4) * 16;
    const uint32_t vb_off = (warpN * 16 + ((lane >> 4) << 3) + (lane & 7)) * 80 + ((lane >> 3) & 1) * 16;

    for (int c = 0; c < 16; ++c) {
        if (c + 1 < 16) { CP_WAIT1; } else { CP_WAIT0; }
        __syncthreads();
        if (c + 2 < 16) vload(c + 2, (c + 2) % 3);
        const uint32_t vb = smb + FA_VB + (c % 3) * FA_VSTG;
        #pragma unroll
        for (int ks = 0; ks < 2; ++ks) {
            uint32_t ar[2][4], vh4[4];
            #pragma unroll
            for (int i = 0; i < 2; ++i)
                ldsm4(ar[i], smb + pa_off + c * 5120 + i * (16*80) + ks * 32);
            ldsm4(vh4, vb + vb_off + ks * 32);
            #pragma unroll
            for (int i = 0; i < 2; ++i)
                #pragma unroll
                for (int j = 0; j < 2; ++j) {
                    uint32_t bfh[2] = { vh4[j * 2], vh4[j * 2 + 1] };
                    mma_f16(oac[i][j], ar[i], bfh);
                }
        }
    }

    // epilogue: write attention output (fp16 single)
    #pragma unroll
    for (int i = 0; i < 2; ++i)
        #pragma unroll
        for (int j = 0; j < 2; ++j)
            #pragma unroll
            for (int rr = 0; rr < 2; ++rr) {
                const int m = t0 + warpM * 32 + i * 16 + (lane >> 2) + rr * 8;
                const int cc = warpN * 16 + j * 8 + (lane & 3) * 2;
                *(__half2*)(g_att + (size_t)(b * T + m) * D + h * HS + cc) =
                    __halves2half2(__float2half_rn(oac[i][j][rr*2+0]),
                                   __float2half_rn(oac[i][j][rr*2+1]));
            }
}

// ===================== launch ==============================================
extern "C" void kernel_launch(void* const* d_in, const int* in_sizes, int n_in,
                              void* d_out, int out_size)
{
    (void)in_sizes; (void)n_in; (void)out_size;
    const float* src    = (const float*)d_in[0];
    const float* norm_w = (const float*)d_in[1];
    const float* Wq     = (const float*)d_in[2];
    const float* bq     = (const float*)d_in[3];
    const float* Wk     = (const float*)d_in[4];
    const float* bk     = (const float*)d_in[5];
    const float* Wv     = (const float*)d_in[6];
    const float* bv     = (const float*)d_in[7];
    const float* relp   = (const float*)d_in[8];
    const float* proj_w = (const float*)d_in[9];
    const float* proj_b = (const float*)d_in[10];
    const float* ff_w1  = (const float*)d_in[11];
    const float* ff_b1  = (const float*)d_in[12];
    const float* ff_w2  = (const float*)d_in[13];
    const float* ff_b2  = (const float*)d_in[14];
    float* out = (float*)d_out;

    float *px, *psrc2, *py;
    __half *pxh, *pxl, *pyh, *pyl, *pvth, *patt, *phid;
    __half *ppwh, *ppwl, *pf1h, *pf1l, *pf2h, *pf2l, *pw3h, *pw3l;
    cudaGetSymbolAddress((void**)&px,    g_x);
    cudaGetSymbolAddress((void**)&psrc2, g_src2);
    cudaGetSymbolAddress((void**)&py,    g_y);
    cudaGetSymbolAddress((void**)&pxh,   g_xh);
    cudaGetSymbolAddress((void**)&pxl,   g_xl);
    cudaGetSymbolAddress((void**)&pyh,   g_yh);
    cudaGetSymbolAddress((void**)&pyl,   g_yl);
    cudaGetSymbolAddress((void**)&pvth,  g_vth);
    cudaGetSymbolAddress((void**)&patt,  g_att);
    cudaGetSymbolAddress((void**)&phid,  g_hid);
    cudaGetSymbolAddress((void**)&pw3h,  g_w3h);
    cudaGetSymbolAddress((void**)&pw3l,  g_w3l);
    cudaGetSymbolAddress((void**)&ppwh,  g_pwh);
    cudaGetSymbolAddress((void**)&ppwl,  g_pwl);
    cudaGetSymbolAddress((void**)&pf1h,  g_f1h);
    cudaGetSymbolAddress((void**)&pf1l,  g_f1l);
    cudaGetSymbolAddress((void**)&pf2h,  g_f2h);
    cudaGetSymbolAddress((void**)&pf2l,  g_f2l);

    cudaFuncSetAttribute(gemm_qk, cudaFuncAttributeMaxDynamicSharedMemorySize, G3_SMEM);
    cudaFuncSetAttribute(gemmN<1,false,false,false,false,true>,  cudaFuncAttributeMaxDynamicSharedMemorySize, G1_SMEM);
    cudaFuncSetAttribute(gemmN<1,true, false,true, false,false>, cudaFuncAttributeMaxDynamicSharedMemorySize, G1_SMEM);
    cudaFuncSetAttribute(gemmN<1,false,true, false,true, false>, cudaFuncAttributeMaxDynamicSharedMemorySize, G1_SMEM);
    cudaFuncSetAttribute(fused_attn, cudaFuncAttributeMaxDynamicSharedMemorySize, FA_SMEM);

    // weight prep
    wsplit_qkv_t<<<dim3(D/32, HS/32, 24), 256>>>(Wq, Wk, Wv);
    wsplit_t<<<dim3(D/32, D/32),  256>>>(proj_w, ppwh, ppwl, D, D);
    wsplit_t<<<dim3(FF/32, D/32), 256>>>(ff_w1, pf1h, pf1l, D, FF);
    wsplit_t<<<dim3(D/32, FF/32), 256>>>(ff_w2, pf2h, pf2l, FF, D);

    // x = rmsnorm(src)
    rmsnorm_kernel<<<BT, 128>>>(src, norm_w, px, pxh, pxl);

    // q (fp32 + hi/lo) and k8 (hi/lo) in one launch (3-product)
    gemm_qk<<<dim3(D/128, BT/128, 2), 256, G3_SMEM>>>(bq, bk);
    // v: transposed single fp16 (1-product)
    gemmN<1,false,false,false,false,true><<<dim3(D/128, BT/128), 256, G1_SMEM>>>(
        pxh, pw3h + 2*D*D, nullptr, bv, nullptr, nullptr, pvth, BT, D, D, 1.f);

    // attention
    rel_kernel<<<dim3(T, H), 256>>>(relp);
    fused_attn<<<dim3(T/64, BATCH*H), 256, FA_SMEM>>>();

    // src2 = x + att @ proj_w + proj_b  (1-product)
    gemmN<1,true,false,true,false,false><<<dim3(D/128, BT/128), 256, G1_SMEM>>>(
        patt, ppwh, nullptr, proj_b, px, psrc2, nullptr, BT, D, D, 1.f);

    // y = rmsnorm(src2)
    rmsnorm_kernel<<<BT, 128>>>(psrc2, norm_w, py, pyh, pyl);

    // h = gelu(y @ ff_w1 + ff_b1)  (1-product)
    gemmN<1,false,true,false,true,false><<<dim3(FF/128, BT/128), 256, G1_SMEM>>>(
        pyh, pf1h, nullptr, ff_b1, nullptr, nullptr, phid, BT, FF, D, 1.f);

    // out = y + h @ ff_w2 + ff_b2  (1-product)
    gemmN<1,true,false,true,false,false><<<dim3(D/128, BT/128), 256, G1_SMEM>>>(
        phid, pf2h, nullptr, ff_b2, py, out, nullptr, BT, D, FF, 1.f);
}